// round 13
// baseline (speedup 1.0000x reference)
#include <cuda_runtime.h>
#include <cstdint>

#define NB 2
#define NC 512
#define NH 32
#define NW 32
#define HW 1024
#define NG 8
#define DH 64
#define BG 16
#define JD 64
#define EPSBN 1e-5f

#define TABN 129
#define FMAXF 1.43f
#define TSTEP (2.0f*FMAXF/128.0f)
#define TINV  (128.0f/(2.0f*FMAXF))

// ---------------- scratch ----------------
__device__ float g_q[NB*NC*HW];
__device__ float g_qt[BG*HW*DH];     // transposed q: [bg][pixel][ch]
__device__ float g_grid[BG*JD*2];
__device__ float g_k[BG*DH*JD];
__device__ float g_v[BG*DH*JD];
__device__ float g_bias[BG*HW*JD];   // [bg][j][i]
__device__ float g_attn[NB*NC*HW];
__device__ float g_x2[NB*NC*HW];
__device__ float g_xn2[NB*NC*HW];
__device__ float g_h1[NB*2048*HW];
__device__ float g_tab[TABN*TABN];

__device__ __forceinline__ float gelu_exact(float x){
    return 0.5f*x*(1.0f+erff(x*0.7071067811865476f));
}
__device__ __forceinline__ uint32_t f2tf(float v){
    uint32_t r; asm("cvt.rna.tf32.f32 %0, %1;" : "=r"(r) : "f"(v)); return r;
}
__device__ __forceinline__ float tfr(float v){ return __uint_as_float(f2tf(v)); }
__device__ __forceinline__ void mma_tf32(float c[4], const uint32_t a[4], const uint32_t b[2]){
    asm volatile("mma.sync.aligned.m16n8k8.row.col.f32.tf32.tf32.f32 "
        "{%0,%1,%2,%3}, {%4,%5,%6,%7}, {%8,%9}, {%0,%1,%2,%3};"
        : "+f"(c[0]),"+f"(c[1]),"+f"(c[2]),"+f"(c[3])
        : "r"(a[0]),"r"(a[1]),"r"(a[2]),"r"(a[3]),"r"(b[0]),"r"(b[1]));
}
__device__ __forceinline__ void cpa16(float* smem, const float* gmem){
    uint32_t s = (uint32_t)__cvta_generic_to_shared(smem);
    asm volatile("cp.async.ca.shared.global [%0], [%1], 16;" :: "r"(s), "l"(gmem));
}

// ---------------- 1) q grouped 1x1 conv, bn1 fused into load ----------------
__global__ void k_qproj(const float* __restrict__ x, const float* __restrict__ qw,
                        const float* __restrict__ g1, const float* __restrict__ b1){
    __shared__ float ws[DH*DH];
    __shared__ float xs[DH*128];
    int bg = blockIdx.y; int b = bg>>3, g = bg&7;
    int p0 = blockIdx.x*128;
    int tid = threadIdx.x;
    const float* wsrc = qw + g*DH*DH;
    for(int i=tid;i<DH*DH;i+=128) ws[i]=wsrc[i];
    const float* xsrc = x + (b*NC + g*DH)*HW + p0;
    for(int k=0;k<DH;k++){
        int c = g*DH + k;
        float s = g1[c]*rsqrtf(1.0f+EPSBN);
        float bb = b1[c];
        xs[k*128+tid] = xsrc[k*HW+tid]*s + bb;
    }
    __syncthreads();
    float acc[DH];
    #pragma unroll
    for(int o=0;o<DH;o++) acc[o]=0.f;
    for(int c=0;c<DH;c++){
        float xv = xs[c*128+tid];
        #pragma unroll
        for(int o=0;o<DH;o++) acc[o] += ws[o*DH+c]*xv;
    }
    float* qdst = g_q + (b*NC + g*DH)*HW + p0 + tid;
    #pragma unroll
    for(int o=0;o<DH;o++) qdst[o*HW]=acc[o];
    float* qt = g_qt + (bg*HW + p0 + tid)*DH;
    #pragma unroll
    for(int o=0;o<DH;o+=4)
        *(float4*)&qt[o] = make_float4(acc[o],acc[o+1],acc[o+2],acc[o+3]);
}

// ---------------- 2) offsets: TWO warps per (bg,pos), taps split by ky ----------------
__global__ void __launch_bounds__(256) k_offsets(
        const float* __restrict__ dw, const float* __restrict__ dwb,
        const float* __restrict__ pw){
    __shared__ float dwt[36*DH];      // [tap][ch]
    __shared__ float pws[2*DH];
    __shared__ float dbs[DH];
    __shared__ float h0[8][32], h1[8][32];
    int tid = threadIdx.x;
    for(int i=tid;i<DH*36;i+=256){ int ch=i/36, tap=i%36; dwt[tap*DH+ch]=dw[i]; }
    for(int i=tid;i<2*DH;i+=256) pws[i]=pw[i];
    for(int i=tid;i<DH;i+=256) dbs[i]=dwb[i];
    __syncthreads();
    int wid = tid>>5, lane = tid&31;
    int pl = wid>>1;                  // 0..3 pos slot in block
    int par = wid&1;                  // tap half
    int gidx = blockIdx.x*4 + pl;     // 0..1023
    int bg = gidx>>6, pos = gidx&63;
    int oy=pos>>3, ox=pos&7;
    int c0 = lane*2;
    const float* qt = g_qt + bg*HW*DH;
    float s0=0.f, s1=0.f;
    int ky0 = par*3;
    #pragma unroll
    for(int kk=0;kk<3;kk++){
        int ky = ky0+kk;
        int iy = oy*4-1+ky;
        if(iy<0||iy>=NH) continue;
        #pragma unroll
        for(int kx=0;kx<6;kx++){
            int ix = ox*4-1+kx;
            if(ix<0||ix>=NW) continue;
            float2 v = *(const float2*)&qt[(iy*NW+ix)*DH + c0];
            float2 w = *(const float2*)&dwt[(ky*6+kx)*DH + c0];
            s0 += v.x*w.x;
            s1 += v.y*w.y;
        }
    }
    h0[wid][lane]=s0; h1[wid][lane]=s1;
    __syncthreads();
    if(par==0){
        float t0 = s0 + h0[wid+1][lane];
        float t1 = s1 + h1[wid+1][lane];
        t0 = gelu_exact(t0 + dbs[c0]);
        t1 = gelu_exact(t1 + dbs[c0+1]);
        float a0 = t0*pws[c0]    + t1*pws[c0+1];
        float a1 = t0*pws[DH+c0] + t1*pws[DH+c0+1];
        #pragma unroll
        for(int o=16;o>0;o>>=1){
            a0 += __shfl_xor_sync(0xffffffffu, a0, o);
            a1 += __shfl_xor_sync(0xffffffffu, a1, o);
        }
        if(lane==0){
            float vx = (float)ox + tanhf(a0)*4.0f;
            float vy = (float)oy + tanhf(a1)*4.0f;
            g_grid[(bg*JD+pos)*2+0] = 2.0f*vx/7.0f - 1.0f;
            g_grid[(bg*JD+pos)*2+1] = 2.0f*vy/7.0f - 1.0f;
        }
    }
}

// ---------------- 3) grid_sample (bn fused) + k/v conv; o-dim split in 2 ----------------
__global__ void k_sample(const float* __restrict__ x,
                         const float* __restrict__ kw, const float* __restrict__ vw,
                         const float* __restrict__ g1, const float* __restrict__ b1){
    __shared__ float kvs[DH*8];
    __shared__ float kws[32*DH];
    __shared__ float vws[32*DH];
    __shared__ float scs[DH], bcs[DH];
    int bg=blockIdx.x, jq=blockIdx.y, oh=blockIdx.z*32, tid=threadIdx.x;
    int b=bg>>3, g=bg&7;
    for(int i=tid;i<32*DH;i+=256){ kws[i]=kw[g*DH*DH+oh*DH+i]; vws[i]=vw[g*DH*DH+oh*DH+i]; }
    if(tid<DH){
        int c = g*DH + tid;
        scs[tid] = g1[c]*rsqrtf(1.0f+EPSBN);
        bcs[tid] = b1[c];
    }
    __syncthreads();
    const float* img = x + (b*NC+g*DH)*HW;
    for(int i=tid;i<DH*8;i+=256){
        int c=i>>3, jl=i&7, j=jq*8+jl;
        float s=scs[c], bb=bcs[c];
        float nx=g_grid[(bg*JD+j)*2], ny=g_grid[(bg*JD+j)*2+1];
        float gx=(nx+1.0f)*16.0f-0.5f;
        float gy2=(ny+1.0f)*16.0f-0.5f;
        float x0f=floorf(gx), y0f=floorf(gy2);
        float wx=gx-x0f, wy=gy2-y0f;
        int x0=(int)x0f, y0=(int)y0f;
        const float* im=img+c*HW;
        float v00=0.f,v01=0.f,v10=0.f,v11=0.f;
        bool xi0 = (x0>=0)&&(x0<NW), xi1 = (x0+1>=0)&&(x0+1<NW);
        bool yi0 = (y0>=0)&&(y0<NH), yi1 = (y0+1>=0)&&(y0+1<NH);
        if(yi0){ if(xi0) v00=im[y0*NW+x0]*s+bb; if(xi1) v01=im[y0*NW+x0+1]*s+bb; }
        if(yi1){ if(xi0) v10=im[(y0+1)*NW+x0]*s+bb; if(xi1) v11=im[(y0+1)*NW+x0+1]*s+bb; }
        kvs[c*8+jl] = v00*(1.f-wx)*(1.f-wy)+v01*wx*(1.f-wy)+v10*(1.f-wx)*wy+v11*wx*wy;
    }
    __syncthreads();
    {
        int ol=tid>>3, jl=tid&7, o=oh+ol, j=jq*8+jl;
        float ka=0.f,va=0.f;
        for(int c=0;c<DH;c++){
            float kvv=kvs[c*8+jl];
            ka += kws[ol*DH+c]*kvv;
            va += vws[ol*DH+c]*kvv;
        }
        g_k[bg*DH*JD + o*JD + j] = ka;
        g_v[bg*DH*JD + o*JD + j] = va;
    }
}

// ---------------- 4) CPB table on 129x129 feature grid (mma) ----------------
__global__ void __launch_bounds__(512,1) k_tab(
        const float* __restrict__ w1, const float* __restrict__ b1,
        const float* __restrict__ w2, const float* __restrict__ b2,
        const float* __restrict__ w3, const float* __restrict__ b3){
    extern __shared__ float sm[];
    float* Hs  = sm;
    float* Ws  = Hs + 256*132;
    float* red = Ws + 128*132;
    float* f0s = red + 1024;
    float* f1s = f0s + 256;
    float* b2s = f1s + 256;
    float* w3s = b2s + 128;
    float* w1s = w3s + 128;
    float* b1s = w1s + 256;
    int tid = threadIdx.x;
    int pt0 = blockIdx.x*256;
    if(tid<256){
        int pt = pt0 + tid;
        int v = pt/TABN;
        int u = pt - v*TABN;
        f0s[tid] = -FMAXF + (float)u*TSTEP;
        f1s[tid] = -FMAXF + (float)v*TSTEP;
        w1s[tid] = w1[tid];
    }
    if(tid<128){ b1s[tid]=b1[tid]; b2s[tid]=b2[tid]; w3s[tid]=w3[tid]; }
    #pragma unroll
    for(int it=0; it<8; it++){
        int idx = tid + it*512;
        int k = idx>>5, n4 = (idx&31)*4;
        float4 v = *(const float4*)&w2[k*128 + n4];
        *(float4*)&Ws[k*132 + n4] = make_float4(tfr(v.x),tfr(v.y),tfr(v.z),tfr(v.w));
    }
    __syncthreads();
    #pragma unroll
    for(int it=0; it<16; it++){
        int idx = tid + it*512;
        int m = idx>>5, k4 = (idx&31)*4;
        float f0 = f0s[m], f1 = f1s[m];
        float4 wv0 = *(const float4*)&w1s[k4];
        float4 wv1 = *(const float4*)&w1s[128+k4];
        float4 bv  = *(const float4*)&b1s[k4];
        float4 h;
        h.x = tfr(fmaxf(f0*wv0.x + f1*wv1.x + bv.x, 0.f));
        h.y = tfr(fmaxf(f0*wv0.y + f1*wv1.y + bv.y, 0.f));
        h.z = tfr(fmaxf(f0*wv0.z + f1*wv1.z + bv.z, 0.f));
        h.w = tfr(fmaxf(f0*wv0.w + f1*wv1.w + bv.w, 0.f));
        *(float4*)&Hs[m*132 + k4] = h;
    }
    __syncthreads();

    int lane = tid&31, wid = tid>>5;
    int g = lane>>2, t = lane&3;
    int mbase = (wid&3)*64, nbase = (wid>>2)*32;
    float acc[4][4][4];
    #pragma unroll
    for(int a=0;a<4;a++){
        #pragma unroll
        for(int nn=0;nn<4;nn++){
            #pragma unroll
            for(int cc=0;cc<4;cc++) acc[a][nn][cc]=0.f; } }

    #pragma unroll 4
    for(int kc=0;kc<16;kc++){
        int K = kc*8;
        uint32_t af[4][4];
        #pragma unroll
        for(int mt=0;mt<4;mt++){
            const float* ap = Hs + (mbase+mt*16+g)*132 + K + t;
            af[mt][0] = __float_as_uint(ap[0]);
            af[mt][1] = __float_as_uint(ap[8*132]);
            af[mt][2] = __float_as_uint(ap[4]);
            af[mt][3] = __float_as_uint(ap[8*132+4]);
        }
        uint32_t bf[4][2];
        #pragma unroll
        for(int nt=0;nt<4;nt++){
            const float* bp = Ws + (K+t)*132 + nbase + nt*8 + g;
            bf[nt][0] = __float_as_uint(bp[0]);
            bf[nt][1] = __float_as_uint(bp[4*132]);
        }
        #pragma unroll
        for(int mt=0;mt<4;mt++){
            #pragma unroll
            for(int nt=0;nt<4;nt++) mma_tf32(acc[mt][nt], af[mt], bf[nt]);
        }
    }
    #pragma unroll
    for(int mt=0;mt<4;mt++){
        float pA=0.f, pB=0.f;
        #pragma unroll
        for(int nt=0;nt<4;nt++){
            int n = nbase + nt*8 + 2*t;
            float ba=b2s[n], bb=b2s[n+1], wa=w3s[n], wb=w3s[n+1];
            pA += fmaxf(acc[mt][nt][0]+ba,0.f)*wa + fmaxf(acc[mt][nt][1]+bb,0.f)*wb;
            pB += fmaxf(acc[mt][nt][2]+ba,0.f)*wa + fmaxf(acc[mt][nt][3]+bb,0.f)*wb;
        }
        pA += __shfl_xor_sync(0xffffffffu, pA, 1);
        pA += __shfl_xor_sync(0xffffffffu, pA, 2);
        pB += __shfl_xor_sync(0xffffffffu, pB, 1);
        pB += __shfl_xor_sync(0xffffffffu, pB, 2);
        if(t==0){
            int rA = mbase+mt*16+g;
            red[rA*4 + (wid>>2)]     = pA;
            red[(rA+8)*4 + (wid>>2)] = pB;
        }
    }
    __syncthreads();
    if(tid<256 && pt0+tid<TABN*TABN)
        g_tab[pt0+tid] = b3[0] + red[tid*4] + red[tid*4+1] + red[tid*4+2] + red[tid*4+3];
}

// ---------------- 5) bias interpolation -> g_bias [bg][j][i] ----------------
__global__ void k_interp(){
    int idx = blockIdx.x*256 + threadIdx.x;
    int bg = idx>>16;
    int j  = (idx>>10)&63;
    int i  = idx&1023;
    float qx = 2.0f*(float)(i&31)*(1.0f/31.0f) - 1.0f;
    float qy = 2.0f*(float)(i>>5)*(1.0f/31.0f) - 1.0f;
    float2 kv = *(const float2*)&g_grid[(bg*JD+j)*2];
    float p0 = qx - kv.x, p1 = qy - kv.y;
    float f0 = copysignf(log1pf(fabsf(p0)), p0);
    float f1 = copysignf(log1pf(fabsf(p1)), p1);
    float u = fminf(fmaxf((f0+FMAXF)*TINV, 0.0f), 127.999f);
    float v = fminf(fmaxf((f1+FMAXF)*TINV, 0.0f), 127.999f);
    int iu=(int)u, iv=(int)v;
    float fu=u-(float)iu, fv=v-(float)iv;
    const float* t0 = g_tab + iv*TABN + iu;
    float a = t0[0]    + fu*(t0[1]-t0[0]);
    float b = t0[TABN] + fu*(t0[TABN+1]-t0[TABN]);
    g_bias[idx] = a + fv*(b-a);
}

// ---------------- 6) attention ----------------
__global__ void k_attn(){
    __shared__ float ks[DH*JD];
    __shared__ float vs[DH*JD];
    int bg=blockIdx.y, it=blockIdx.x, tid=threadIdx.x;
    int b=bg>>3, g=bg&7;
    for(int i=tid;i<DH*JD;i+=128){ ks[i]=g_k[bg*DH*JD+i]; vs[i]=g_v[bg*DH*JD+i]; }
    __syncthreads();
    int i = it*128 + tid;
    const float* qp = g_q + (b*NC+g*DH)*HW + i;
    float sim[JD];
    #pragma unroll
    for(int j=0;j<JD;j++) sim[j]=0.f;
    for(int d=0;d<DH;d++){
        float qv = qp[d*HW];
        #pragma unroll
        for(int j=0;j<JD;j++) sim[j] += qv*ks[d*JD+j];
    }
    const float scale = 0.125f;
    const float* bp = g_bias + bg*JD*HW + i;
    float m=-1e30f;
    #pragma unroll
    for(int j=0;j<JD;j++){ sim[j] = sim[j]*scale + bp[j*HW]; m=fmaxf(m,sim[j]); }
    float ssum=0.f;
    #pragma unroll
    for(int j=0;j<JD;j++){ sim[j]=expf(sim[j]-m); ssum+=sim[j]; }
    float inv = 1.0f/ssum;
    float* op = g_attn + (b*NC+g*DH)*HW + i;
    for(int d=0;d<DH;d++){
        float a=0.f;
        #pragma unroll
        for(int j=0;j<JD;j++) a += sim[j]*vs[d*JD+j];
        op[d*HW] = a*inv;
    }
}

// ---------------- 3-buffer cp.async tf32 GEMM core, ONE sync/stage ----------------
template<int MT, int KTOT>
__device__ __forceinline__ void gemm_core(const float* __restrict__ A,
                                          const float* __restrict__ Bb,
                                          int m0, int p0,
                                          float* As, float* Bs,
                                          float (*acc)[4][4]){
    constexpr int BM = MT*32;
    constexpr int NA = BM/32;
    constexpr int NS = KTOT/32;
    constexpr int ASTR = BM*36;
    constexpr int BSTR = 32*132;
    int tid=threadIdx.x, lane=tid&31, wid=tid>>5;
    int g=lane>>2, t=lane&3;
    int mbase=(wid&1)*MT*16, nbase=(wid>>1)*32;

    auto prefetch = [&](int s, int buf){
        int k0 = s*32;
        float* Ad = As + buf*ASTR;
        float* Bd = Bs + buf*BSTR;
        #pragma unroll
        for(int ia=0; ia<NA; ia++){
            int idx = tid + ia*256;
            cpa16(Ad + (idx>>3)*36 + (idx&7)*4, A + (m0+(idx>>3))*KTOT + k0 + (idx&7)*4);
        }
        #pragma unroll
        for(int ib=0; ib<4; ib++){
            int idx = tid + ib*256;
            cpa16(Bd + (idx>>5)*132 + (idx&31)*4, Bb + (k0+(idx>>5))*HW + p0 + (idx&31)*4);
        }
        asm volatile("cp.async.commit_group;");
    };

    prefetch(0,0);
    if(NS>1) prefetch(1,1);
    int cb = 0, nb = 2;
    for(int s=0; s<NS; s++){
        if(s+1<NS) asm volatile("cp.async.wait_group 1;");
        else       asm volatile("cp.async.wait_group 0;");
        __syncthreads();
        // buffer nb was last consumed in stage s-2 (readers done by this sync)
        if(s+2<NS) prefetch(s+2, nb);
        const float* Ac = As + cb*ASTR;
        const float* Bc = Bs + cb*BSTR;
        #pragma unroll
        for(int kc=0;kc<4;kc++){
            int K = kc*8;
            uint32_t af[MT][4];
            #pragma unroll
            for(int mt=0;mt<MT;mt++){
                const float* ap = Ac + (mbase+mt*16+g)*36 + K + t;
                af[mt][0] = __float_as_uint(ap[0]);
                af[mt][1] = __float_as_uint(ap[8*36]);
                af[mt][2] = __float_as_uint(ap[4]);
                af[mt][3] = __float_as_uint(ap[8*36+4]);
            }
            uint32_t bf[4][2];
            #pragma unroll
            for(int nt=0;nt<4;nt++){
                const float* bp = Bc + (K+t)*132 + nbase + nt*8 + g;
                bf[nt][0] = __float_as_uint(bp[0]);
                bf[nt][1] = __float_as_uint(bp[4*132]);
            }
            #pragma unroll
            for(int mt=0;mt<MT;mt++){
                #pragma unroll
                for(int nt=0;nt<4;nt++) mma_tf32(acc[mt][nt], af[mt], bf[nt]);
            }
        }
        cb = (cb==2)?0:cb+1;
        nb = (nb==2)?0:nb+1;
    }
}

// ---------------- 7) out projection + residual + fused bn2 ----------------
__global__ void __launch_bounds__(256,2) k_outproj(
        const float* __restrict__ ow, const float* __restrict__ ob,
        const float* __restrict__ x, const float* __restrict__ g2,
        const float* __restrict__ bb2){
    extern __shared__ float smp[];
    float* As = smp;
    float* Bs = smp + 3*64*36;
    int m0 = blockIdx.y*64, n0 = blockIdx.x*128;
    int b = n0>>10, p0 = n0&1023;
    float acc[2][4][4];
    #pragma unroll
    for(int a=0;a<2;a++){ 
        #pragma unroll
        for(int nn=0;nn<4;nn++){ 
            #pragma unroll
            for(int cc=0;cc<4;cc++) acc[a][nn][cc]=0.f; } }
    gemm_core<2,512>(ow, g_attn + b*NC*HW, m0, p0, As, Bs, acc);
    int tid=threadIdx.x, lane=tid&31, wid=tid>>5;
    int g=lane>>2, t=lane&3;
    int mbase=(wid&1)*32, nbase=(wid>>1)*32;
    #pragma unroll
    for(int mt=0;mt<2;mt++){
        int mr = m0 + mbase + mt*16 + g;
        float bi0=ob[mr], bi1=ob[mr+8];
        float s0=g2[mr]*rsqrtf(1.0f+EPSBN), s1=g2[mr+8]*rsqrtf(1.0f+EPSBN);
        float c0=bb2[mr], c1=bb2[mr+8];
        #pragma unroll
        for(int nt=0;nt<4;nt++){
            int n = p0 + nbase + nt*8 + 2*t;
            int off0 = (b*NC + mr)*HW + n;
            int off1 = (b*NC + mr+8)*HW + n;
            float2 xv0 = *(const float2*)&x[off0];
            float2 xv1 = *(const float2*)&x[off1];
            float2 v0 = { xv0.x + acc[mt][nt][0] + bi0, xv0.y + acc[mt][nt][1] + bi0 };
            float2 v1 = { xv1.x + acc[mt][nt][2] + bi1, xv1.y + acc[mt][nt][3] + bi1 };
            *(float2*)&g_x2[off0] = v0;
            *(float2*)&g_x2[off1] = v1;
            float2 n0v = { v0.x*s0+c0, v0.y*s0+c0 };
            float2 n1v = { v1.x*s1+c1, v1.y*s1+c1 };
            *(float2*)&g_xn2[off0] = n0v;
            *(float2*)&g_xn2[off1] = n1v;
        }
    }
}

// ---------------- 8) MLP conv1 ----------------
__global__ void __launch_bounds__(256,2) k_mlp1(
        const float* __restrict__ w, const float* __restrict__ bias){
    extern __shared__ float smp[];
    float* As = smp;
    float* Bs = smp + 3*128*36;
    int m0 = blockIdx.y*128, n0 = blockIdx.x*128;
    int b = n0>>10, p0 = n0&1023;
    float acc[4][4][4];
    #pragma unroll
    for(int a=0;a<4;a++){ 
        #pragma unroll
        for(int nn=0;nn<4;nn++){ 
            #pragma unroll
            for(int cc=0;cc<4;cc++) acc[a][nn][cc]=0.f; } }
    gemm_core<4,512>(w, g_xn2 + b*NC*HW, m0, p0, As, Bs, acc);
    int tid=threadIdx.x, lane=tid&31, wid=tid>>5;
    int g=lane>>2, t=lane&3;
    int mbase=(wid&1)*64, nbase=(wid>>1)*32;
    #pragma unroll
    for(int mt=0;mt<4;mt++){
        int mr = m0 + mbase + mt*16 + g;
        float bi0=bias[mr], bi1=bias[mr+8];
        #pragma unroll
        for(int nt=0;nt<4;nt++){
            int n = p0 + nbase + nt*8 + 2*t;
            float2 v0 = { gelu_exact(acc[mt][nt][0]+bi0), gelu_exact(acc[mt][nt][1]+bi0) };
            float2 v1 = { gelu_exact(acc[mt][nt][2]+bi1), gelu_exact(acc[mt][nt][3]+bi1) };
            *(float2*)&g_h1[(b*2048 + mr)*HW + n]   = v0;
            *(float2*)&g_h1[(b*2048 + mr+8)*HW + n] = v1;
        }
    }
}

// ---------------- 9) MLP conv2 + residual ----------------
__global__ void __launch_bounds__(256,2) k_mlp2(
        const float* __restrict__ w, const float* __restrict__ bias,
        float* __restrict__ out){
    extern __shared__ float smp[];
    float* As = smp;
    float* Bs = smp + 3*64*36;
    int m0 = blockIdx.y*64, n0 = blockIdx.x*128;
    int b = n0>>10, p0 = n0&1023;
    float acc[2][4][4];
    #pragma unroll
    for(int a=0;a<2;a++){ 
        #pragma unroll
        for(int nn=0;nn<4;nn++){ 
            #pragma unroll
            for(int cc=0;cc<4;cc++) acc[a][nn][cc]=0.f; } }
    gemm_core<2,2048>(w, g_h1 + b*2048*HW, m0, p0, As, Bs, acc);
    int tid=threadIdx.x, lane=tid&31, wid=tid>>5;
    int g=lane>>2, t=lane&3;
    int mbase=(wid&1)*32, nbase=(wid>>1)*32;
    #pragma unroll
    for(int mt=0;mt<2;mt++){
        int mr = m0 + mbase + mt*16 + g;
        float bi0=bias[mr], bi1=bias[mr+8];
        #pragma unroll
        for(int nt=0;nt<4;nt++){
            int n = p0 + nbase + nt*8 + 2*t;
            int off0 = (b*NC + mr)*HW + n;
            int off1 = (b*NC + mr+8)*HW + n;
            float2 r0 = *(const float2*)&g_x2[off0];
            float2 r1 = *(const float2*)&g_x2[off1];
            float2 v0 = { r0.x + acc[mt][nt][0] + bi0, r0.y + acc[mt][nt][1] + bi0 };
            float2 v1 = { r1.x + acc[mt][nt][2] + bi1, r1.y + acc[mt][nt][3] + bi1 };
            *(float2*)&out[off0] = v0;
            *(float2*)&out[off1] = v1;
        }
    }
}

// ---------------- launch ----------------
extern "C" void kernel_launch(void* const* d_in, const int* in_sizes, int n_in,
                              void* d_out, int out_size){
    const float* x    = (const float*)d_in[0];
    const float* bn1g = (const float*)d_in[1];
    const float* bn1b = (const float*)d_in[2];
    const float* bn2g = (const float*)d_in[3];
    const float* bn2b = (const float*)d_in[4];
    const float* qw   = (const float*)d_in[5];
    const float* kw   = (const float*)d_in[6];
    const float* vw   = (const float*)d_in[7];
    const float* ow   = (const float*)d_in[8];
    const float* obv  = (const float*)d_in[9];
    const float* dw   = (const float*)d_in[10];
    const float* dwb  = (const float*)d_in[11];
    const float* pw   = (const float*)d_in[12];
    const float* cw1  = (const float*)d_in[13];
    const float* cb1  = (const float*)d_in[14];
    const float* cw2  = (const float*)d_in[15];
    const float* cb2  = (const float*)d_in[16];
    const float* cw3  = (const float*)d_in[17];
    const float* cb3  = (const float*)d_in[18];
    const float* mw1  = (const float*)d_in[19];
    const float* mb1  = (const float*)d_in[20];
    const float* mw2  = (const float*)d_in[21];
    const float* mb2  = (const float*)d_in[22];
    float* out = (float*)d_out;

    const int tab_smem  = (256*132 + 128*132 + 1024 + 512 + 256 + 256 + 128) * 4;
    const int gem2_smem = (3*64*36 + 3*32*132) * 4;    // 78336
    const int gem4_smem = (3*128*36 + 3*32*132) * 4;   // 105984

    static bool init = false;
    static cudaStream_t s1;
    static cudaEvent_t evF, evOff, evInt;
    if(!init){
        cudaStreamCreateWithFlags(&s1, cudaStreamNonBlocking);
        cudaEventCreateWithFlags(&evF,   cudaEventDisableTiming);
        cudaEventCreateWithFlags(&evOff, cudaEventDisableTiming);
        cudaEventCreateWithFlags(&evInt, cudaEventDisableTiming);
        cudaFuncSetAttribute(k_tab,     cudaFuncAttributeMaxDynamicSharedMemorySize, tab_smem);
        cudaFuncSetAttribute(k_outproj, cudaFuncAttributeMaxDynamicSharedMemorySize, gem2_smem);
        cudaFuncSetAttribute(k_mlp1,    cudaFuncAttributeMaxDynamicSharedMemorySize, gem4_smem);
        cudaFuncSetAttribute(k_mlp2,    cudaFuncAttributeMaxDynamicSharedMemorySize, gem2_smem);
        init = true;
    }

    cudaEventRecord(evF, 0);
    cudaStreamWaitEvent(s1, evF, 0);
    k_tab<<<66,512,tab_smem,s1>>>(cw1,cb1,cw2,cb2,cw3,cb3);

    k_qproj  <<<dim3(8,16),128>>>(x,qw,bn1g,bn1b);
    k_offsets<<<256,256>>>(dw,dwb,pw);
    cudaEventRecord(evOff, 0);

    k_sample <<<dim3(16,8,2),256>>>(x,kw,vw,bn1g,bn1b);

    cudaStreamWaitEvent(s1, evOff, 0);
    k_interp <<<4096,256,0,s1>>>();
    cudaEventRecord(evInt, s1);

    cudaStreamWaitEvent(0, evInt, 0);
    k_attn   <<<dim3(8,16),128>>>();
    k_outproj<<<dim3(16,8),256,gem2_smem>>>(ow,obv,x,bn2g,bn2b);
    k_mlp1   <<<dim3(16,16),256,gem4_smem>>>(mw1,mb1);
    k_mlp2   <<<dim3(16,8),256,gem2_smem>>>(mw2,mb2,out);
}

// round 14
// speedup vs baseline: 1.0009x; 1.0009x over previous
#include <cuda_runtime.h>
#include <cstdint>

#define NB 2
#define NC 512
#define NH 32
#define NW 32
#define HW 1024
#define NG 8
#define DH 64
#define BG 16
#define JD 64
#define EPSBN 1e-5f

#define TABN 129
#define FMAXF 1.43f
#define TSTEP (2.0f*FMAXF/128.0f)
#define TINV  (128.0f/(2.0f*FMAXF))

// ---------------- scratch ----------------
__device__ float g_q[NB*NC*HW];
__device__ float g_qt[BG*HW*DH];
__device__ float g_grid[BG*JD*2];
__device__ float g_k[BG*DH*JD];
__device__ float g_v[BG*DH*JD];
__device__ float g_bias[BG*HW*JD];   // [bg][j][i]
__device__ float g_attn[NB*NC*HW];
__device__ float g_x2[NB*NC*HW];
__device__ float g_xn2[NB*NC*HW];
__device__ float g_h1[NB*2048*HW];
__device__ float g_tab[TABN*TABN];

__device__ __forceinline__ float gelu_exact(float x){
    return 0.5f*x*(1.0f+erff(x*0.7071067811865476f));
}
__device__ __forceinline__ uint32_t f2tf(float v){
    uint32_t r; asm("cvt.rna.tf32.f32 %0, %1;" : "=r"(r) : "f"(v)); return r;
}
__device__ __forceinline__ float tfr(float v){ return __uint_as_float(f2tf(v)); }
__device__ __forceinline__ void mma_tf32(float c[4], const uint32_t a[4], const uint32_t b[2]){
    asm volatile("mma.sync.aligned.m16n8k8.row.col.f32.tf32.tf32.f32 "
        "{%0,%1,%2,%3}, {%4,%5,%6,%7}, {%8,%9}, {%0,%1,%2,%3};"
        : "+f"(c[0]),"+f"(c[1]),"+f"(c[2]),"+f"(c[3])
        : "r"(a[0]),"r"(a[1]),"r"(a[2]),"r"(a[3]),"r"(b[0]),"r"(b[1]));
}
__device__ __forceinline__ void cpa16(float* smem, const float* gmem){
    uint32_t s = (uint32_t)__cvta_generic_to_shared(smem);
    asm volatile("cp.async.ca.shared.global [%0], [%1], 16;" :: "r"(s), "l"(gmem));
}

// ---------------- 1) q grouped 1x1 conv, bn1 fused into load ----------------
__global__ void k_qproj(const float* __restrict__ x, const float* __restrict__ qw,
                        const float* __restrict__ g1, const float* __restrict__ b1){
    __shared__ float ws[DH*DH];
    __shared__ float xs[DH*128];
    int bg = blockIdx.y; int b = bg>>3, g = bg&7;
    int p0 = blockIdx.x*128;
    int tid = threadIdx.x;
    const float* wsrc = qw + g*DH*DH;
    for(int i=tid;i<DH*DH;i+=128) ws[i]=wsrc[i];
    const float* xsrc = x + (b*NC + g*DH)*HW + p0;
    for(int k=0;k<DH;k++){
        int c = g*DH + k;
        float s = g1[c]*rsqrtf(1.0f+EPSBN);
        float bb = b1[c];
        xs[k*128+tid] = xsrc[k*HW+tid]*s + bb;
    }
    __syncthreads();
    float acc[DH];
    #pragma unroll
    for(int o=0;o<DH;o++) acc[o]=0.f;
    for(int c=0;c<DH;c++){
        float xv = xs[c*128+tid];
        #pragma unroll
        for(int o=0;o<DH;o++) acc[o] += ws[o*DH+c]*xv;
    }
    float* qdst = g_q + (b*NC + g*DH)*HW + p0 + tid;
    #pragma unroll
    for(int o=0;o<DH;o++) qdst[o*HW]=acc[o];
    float* qt = g_qt + (bg*HW + p0 + tid)*DH;
    #pragma unroll
    for(int o=0;o<DH;o+=4)
        *(float4*)&qt[o] = make_float4(acc[o],acc[o+1],acc[o+2],acc[o+3]);
}

// ---------------- 2) offsets: TWO warps per (bg,pos), taps split by ky ----------------
__global__ void __launch_bounds__(256) k_offsets(
        const float* __restrict__ dw, const float* __restrict__ dwb,
        const float* __restrict__ pw){
    __shared__ float dwt[36*DH];
    __shared__ float pws[2*DH];
    __shared__ float dbs[DH];
    __shared__ float h0[8][32], h1[8][32];
    int tid = threadIdx.x;
    for(int i=tid;i<DH*36;i+=256){ int ch=i/36, tap=i%36; dwt[tap*DH+ch]=dw[i]; }
    for(int i=tid;i<2*DH;i+=256) pws[i]=pw[i];
    for(int i=tid;i<DH;i+=256) dbs[i]=dwb[i];
    __syncthreads();
    int wid = tid>>5, lane = tid&31;
    int pl = wid>>1;
    int par = wid&1;
    int gidx = blockIdx.x*4 + pl;
    int bg = gidx>>6, pos = gidx&63;
    int oy=pos>>3, ox=pos&7;
    int c0 = lane*2;
    const float* qt = g_qt + bg*HW*DH;
    float s0=0.f, s1=0.f;
    int ky0 = par*3;
    #pragma unroll
    for(int kk=0;kk<3;kk++){
        int ky = ky0+kk;
        int iy = oy*4-1+ky;
        if(iy<0||iy>=NH) continue;
        #pragma unroll
        for(int kx=0;kx<6;kx++){
            int ix = ox*4-1+kx;
            if(ix<0||ix>=NW) continue;
            float2 v = *(const float2*)&qt[(iy*NW+ix)*DH + c0];
            float2 w = *(const float2*)&dwt[(ky*6+kx)*DH + c0];
            s0 += v.x*w.x;
            s1 += v.y*w.y;
        }
    }
    h0[wid][lane]=s0; h1[wid][lane]=s1;
    __syncthreads();
    if(par==0){
        float t0 = s0 + h0[wid+1][lane];
        float t1 = s1 + h1[wid+1][lane];
        t0 = gelu_exact(t0 + dbs[c0]);
        t1 = gelu_exact(t1 + dbs[c0+1]);
        float a0 = t0*pws[c0]    + t1*pws[c0+1];
        float a1 = t0*pws[DH+c0] + t1*pws[DH+c0+1];
        #pragma unroll
        for(int o=16;o>0;o>>=1){
            a0 += __shfl_xor_sync(0xffffffffu, a0, o);
            a1 += __shfl_xor_sync(0xffffffffu, a1, o);
        }
        if(lane==0){
            float vx = (float)ox + tanhf(a0)*4.0f;
            float vy = (float)oy + tanhf(a1)*4.0f;
            g_grid[(bg*JD+pos)*2+0] = 2.0f*vx/7.0f - 1.0f;
            g_grid[(bg*JD+pos)*2+1] = 2.0f*vy/7.0f - 1.0f;
        }
    }
}

// ---------------- 3) grid_sample (bn fused) + k/v conv; o-dim split in 2 ----------------
__global__ void k_sample(const float* __restrict__ x,
                         const float* __restrict__ kw, const float* __restrict__ vw,
                         const float* __restrict__ g1, const float* __restrict__ b1){
    __shared__ float kvs[DH*8];
    __shared__ float kws[32*DH];
    __shared__ float vws[32*DH];
    __shared__ float scs[DH], bcs[DH];
    int bg=blockIdx.x, jq=blockIdx.y, oh=blockIdx.z*32, tid=threadIdx.x;
    int b=bg>>3, g=bg&7;
    for(int i=tid;i<32*DH;i+=256){ kws[i]=kw[g*DH*DH+oh*DH+i]; vws[i]=vw[g*DH*DH+oh*DH+i]; }
    if(tid<DH){
        int c = g*DH + tid;
        scs[tid] = g1[c]*rsqrtf(1.0f+EPSBN);
        bcs[tid] = b1[c];
    }
    __syncthreads();
    const float* img = x + (b*NC+g*DH)*HW;
    for(int i=tid;i<DH*8;i+=256){
        int c=i>>3, jl=i&7, j=jq*8+jl;
        float s=scs[c], bb=bcs[c];
        float nx=g_grid[(bg*JD+j)*2], ny=g_grid[(bg*JD+j)*2+1];
        float gx=(nx+1.0f)*16.0f-0.5f;
        float gy2=(ny+1.0f)*16.0f-0.5f;
        float x0f=floorf(gx), y0f=floorf(gy2);
        float wx=gx-x0f, wy=gy2-y0f;
        int x0=(int)x0f, y0=(int)y0f;
        const float* im=img+c*HW;
        float v00=0.f,v01=0.f,v10=0.f,v11=0.f;
        bool xi0 = (x0>=0)&&(x0<NW), xi1 = (x0+1>=0)&&(x0+1<NW);
        bool yi0 = (y0>=0)&&(y0<NH), yi1 = (y0+1>=0)&&(y0+1<NH);
        if(yi0){ if(xi0) v00=im[y0*NW+x0]*s+bb; if(xi1) v01=im[y0*NW+x0+1]*s+bb; }
        if(yi1){ if(xi0) v10=im[(y0+1)*NW+x0]*s+bb; if(xi1) v11=im[(y0+1)*NW+x0+1]*s+bb; }
        kvs[c*8+jl] = v00*(1.f-wx)*(1.f-wy)+v01*wx*(1.f-wy)+v10*(1.f-wx)*wy+v11*wx*wy;
    }
    __syncthreads();
    {
        int ol=tid>>3, jl=tid&7, o=oh+ol, j=jq*8+jl;
        float ka=0.f,va=0.f;
        for(int c=0;c<DH;c++){
            float kvv=kvs[c*8+jl];
            ka += kws[ol*DH+c]*kvv;
            va += vws[ol*DH+c]*kvv;
        }
        g_k[bg*DH*JD + o*JD + j] = ka;
        g_v[bg*DH*JD + o*JD + j] = va;
    }
}

// ---------------- 4) CPB table on 129x129 feature grid (mma) ----------------
__global__ void __launch_bounds__(512,1) k_tab(
        const float* __restrict__ w1, const float* __restrict__ b1,
        const float* __restrict__ w2, const float* __restrict__ b2,
        const float* __restrict__ w3, const float* __restrict__ b3){
    extern __shared__ float sm[];
    float* Hs  = sm;
    float* Ws  = Hs + 256*132;
    float* red = Ws + 128*132;
    float* f0s = red + 1024;
    float* f1s = f0s + 256;
    float* b2s = f1s + 256;
    float* w3s = b2s + 128;
    float* w1s = w3s + 128;
    float* b1s = w1s + 256;
    int tid = threadIdx.x;
    int pt0 = blockIdx.x*256;
    if(tid<256){
        int pt = pt0 + tid;
        int v = pt/TABN;
        int u = pt - v*TABN;
        f0s[tid] = -FMAXF + (float)u*TSTEP;
        f1s[tid] = -FMAXF + (float)v*TSTEP;
        w1s[tid] = w1[tid];
    }
    if(tid<128){ b1s[tid]=b1[tid]; b2s[tid]=b2[tid]; w3s[tid]=w3[tid]; }
    #pragma unroll
    for(int it=0; it<8; it++){
        int idx = tid + it*512;
        int k = idx>>5, n4 = (idx&31)*4;
        float4 v = *(const float4*)&w2[k*128 + n4];
        *(float4*)&Ws[k*132 + n4] = make_float4(tfr(v.x),tfr(v.y),tfr(v.z),tfr(v.w));
    }
    __syncthreads();
    #pragma unroll
    for(int it=0; it<16; it++){
        int idx = tid + it*512;
        int m = idx>>5, k4 = (idx&31)*4;
        float f0 = f0s[m], f1 = f1s[m];
        float4 wv0 = *(const float4*)&w1s[k4];
        float4 wv1 = *(const float4*)&w1s[128+k4];
        float4 bv  = *(const float4*)&b1s[k4];
        float4 h;
        h.x = tfr(fmaxf(f0*wv0.x + f1*wv1.x + bv.x, 0.f));
        h.y = tfr(fmaxf(f0*wv0.y + f1*wv1.y + bv.y, 0.f));
        h.z = tfr(fmaxf(f0*wv0.z + f1*wv1.z + bv.z, 0.f));
        h.w = tfr(fmaxf(f0*wv0.w + f1*wv1.w + bv.w, 0.f));
        *(float4*)&Hs[m*132 + k4] = h;
    }
    __syncthreads();

    int lane = tid&31, wid = tid>>5;
    int g = lane>>2, t = lane&3;
    int mbase = (wid&3)*64, nbase = (wid>>2)*32;
    float acc[4][4][4];
    #pragma unroll
    for(int a=0;a<4;a++){
        #pragma unroll
        for(int nn=0;nn<4;nn++){
            #pragma unroll
            for(int cc=0;cc<4;cc++) acc[a][nn][cc]=0.f; } }

    #pragma unroll 4
    for(int kc=0;kc<16;kc++){
        int K = kc*8;
        uint32_t af[4][4];
        #pragma unroll
        for(int mt=0;mt<4;mt++){
            const float* ap = Hs + (mbase+mt*16+g)*132 + K + t;
            af[mt][0] = __float_as_uint(ap[0]);
            af[mt][1] = __float_as_uint(ap[8*132]);
            af[mt][2] = __float_as_uint(ap[4]);
            af[mt][3] = __float_as_uint(ap[8*132+4]);
        }
        uint32_t bf[4][2];
        #pragma unroll
        for(int nt=0;nt<4;nt++){
            const float* bp = Ws + (K+t)*132 + nbase + nt*8 + g;
            bf[nt][0] = __float_as_uint(bp[0]);
            bf[nt][1] = __float_as_uint(bp[4*132]);
        }
        #pragma unroll
        for(int mt=0;mt<4;mt++){
            #pragma unroll
            for(int nt=0;nt<4;nt++) mma_tf32(acc[mt][nt], af[mt], bf[nt]);
        }
    }
    #pragma unroll
    for(int mt=0;mt<4;mt++){
        float pA=0.f, pB=0.f;
        #pragma unroll
        for(int nt=0;nt<4;nt++){
            int n = nbase + nt*8 + 2*t;
            float ba=b2s[n], bb=b2s[n+1], wa=w3s[n], wb=w3s[n+1];
            pA += fmaxf(acc[mt][nt][0]+ba,0.f)*wa + fmaxf(acc[mt][nt][1]+bb,0.f)*wb;
            pB += fmaxf(acc[mt][nt][2]+ba,0.f)*wa + fmaxf(acc[mt][nt][3]+bb,0.f)*wb;
        }
        pA += __shfl_xor_sync(0xffffffffu, pA, 1);
        pA += __shfl_xor_sync(0xffffffffu, pA, 2);
        pB += __shfl_xor_sync(0xffffffffu, pB, 1);
        pB += __shfl_xor_sync(0xffffffffu, pB, 2);
        if(t==0){
            int rA = mbase+mt*16+g;
            red[rA*4 + (wid>>2)]     = pA;
            red[(rA+8)*4 + (wid>>2)] = pB;
        }
    }
    __syncthreads();
    if(tid<256 && pt0+tid<TABN*TABN)
        g_tab[pt0+tid] = b3[0] + red[tid*4] + red[tid*4+1] + red[tid*4+2] + red[tid*4+3];
}

// ---------------- 5) bias interpolation -> g_bias [bg][j][i] ----------------
__global__ void k_interp(){
    int idx = blockIdx.x*256 + threadIdx.x;
    int bg = idx>>16;
    int j  = (idx>>10)&63;
    int i  = idx&1023;
    float qx = 2.0f*(float)(i&31)*(1.0f/31.0f) - 1.0f;
    float qy = 2.0f*(float)(i>>5)*(1.0f/31.0f) - 1.0f;
    float2 kv = *(const float2*)&g_grid[(bg*JD+j)*2];
    float p0 = qx - kv.x, p1 = qy - kv.y;
    float f0 = copysignf(log1pf(fabsf(p0)), p0);
    float f1 = copysignf(log1pf(fabsf(p1)), p1);
    float u = fminf(fmaxf((f0+FMAXF)*TINV, 0.0f), 127.999f);
    float v = fminf(fmaxf((f1+FMAXF)*TINV, 0.0f), 127.999f);
    int iu=(int)u, iv=(int)v;
    float fu=u-(float)iu, fv=v-(float)iv;
    const float* t0 = g_tab + iv*TABN + iu;
    float a = t0[0]    + fu*(t0[1]-t0[0]);
    float b = t0[TABN] + fu*(t0[TABN+1]-t0[TABN]);
    g_bias[idx] = a + fv*(b-a);
}

// ---------------- 6) attention (per-batch) ----------------
__global__ void k_attn(int bb){
    __shared__ float ks[DH*JD];
    __shared__ float vs[DH*JD];
    int g=blockIdx.y, it=blockIdx.x, tid=threadIdx.x;
    int bg = bb*8 + g;
    for(int i=tid;i<DH*JD;i+=128){ ks[i]=g_k[bg*DH*JD+i]; vs[i]=g_v[bg*DH*JD+i]; }
    __syncthreads();
    int i = it*128 + tid;
    const float* qp = g_q + (bb*NC+g*DH)*HW + i;
    float sim[JD];
    #pragma unroll
    for(int j=0;j<JD;j++) sim[j]=0.f;
    for(int d=0;d<DH;d++){
        float qv = qp[d*HW];
        #pragma unroll
        for(int j=0;j<JD;j++) sim[j] += qv*ks[d*JD+j];
    }
    const float scale = 0.125f;
    const float* bp = g_bias + bg*JD*HW + i;
    float m=-1e30f;
    #pragma unroll
    for(int j=0;j<JD;j++){ sim[j] = sim[j]*scale + bp[j*HW]; m=fmaxf(m,sim[j]); }
    float ssum=0.f;
    #pragma unroll
    for(int j=0;j<JD;j++){ sim[j]=expf(sim[j]-m); ssum+=sim[j]; }
    float inv = 1.0f/ssum;
    float* op = g_attn + (bb*NC+g*DH)*HW + i;
    for(int d=0;d<DH;d++){
        float a=0.f;
        #pragma unroll
        for(int j=0;j<JD;j++) a += sim[j]*vs[d*JD+j];
        op[d*HW] = a*inv;
    }
}

// ---------------- 2-buffer cp.async tf32 GEMM core (r12, proven) ----------------
template<int MT, int KTOT>
__device__ __forceinline__ void gemm_core(const float* __restrict__ A,
                                          const float* __restrict__ Bb,
                                          int m0, int p0,
                                          float* As, float* Bs,
                                          float (*acc)[4][4]){
    constexpr int BM = MT*32;
    constexpr int NA = BM/32;
    constexpr int NS = KTOT/32;
    int tid=threadIdx.x, lane=tid&31, wid=tid>>5;
    int g=lane>>2, t=lane&3;
    int mbase=(wid&1)*MT*16, nbase=(wid>>1)*32;

    auto prefetch = [&](int s, int buf){
        int k0 = s*32;
        float* Ad = As + buf*BM*36;
        float* Bd = Bs + buf*32*132;
        #pragma unroll
        for(int ia=0; ia<NA; ia++){
            int idx = tid + ia*256;
            cpa16(Ad + (idx>>3)*36 + (idx&7)*4, A + (m0+(idx>>3))*KTOT + k0 + (idx&7)*4);
        }
        #pragma unroll
        for(int ib=0; ib<4; ib++){
            int idx = tid + ib*256;
            cpa16(Bd + (idx>>5)*132 + (idx&31)*4, Bb + (k0+(idx>>5))*HW + p0 + (idx&31)*4);
        }
        asm volatile("cp.async.commit_group;");
    };

    prefetch(0,0);
    for(int s=0; s<NS; s++){
        if(s+1<NS){
            prefetch(s+1,(s+1)&1);
            asm volatile("cp.async.wait_group 1;");
        } else {
            asm volatile("cp.async.wait_group 0;");
        }
        __syncthreads();
        const float* Ac = As + (s&1)*BM*36;
        const float* Bc = Bs + (s&1)*32*132;
        #pragma unroll
        for(int kc=0;kc<4;kc++){
            int K = kc*8;
            uint32_t af[MT][4];
            #pragma unroll
            for(int mt=0;mt<MT;mt++){
                const float* ap = Ac + (mbase+mt*16+g)*36 + K + t;
                af[mt][0] = __float_as_uint(ap[0]);
                af[mt][1] = __float_as_uint(ap[8*36]);
                af[mt][2] = __float_as_uint(ap[4]);
                af[mt][3] = __float_as_uint(ap[8*36+4]);
            }
            uint32_t bf[4][2];
            #pragma unroll
            for(int nt=0;nt<4;nt++){
                const float* bp = Bc + (K+t)*132 + nbase + nt*8 + g;
                bf[nt][0] = __float_as_uint(bp[0]);
                bf[nt][1] = __float_as_uint(bp[4*132]);
            }
            #pragma unroll
            for(int mt=0;mt<MT;mt++){
                #pragma unroll
                for(int nt=0;nt<4;nt++) mma_tf32(acc[mt][nt], af[mt], bf[nt]);
            }
        }
        __syncthreads();
    }
}

// ---------------- 7) out projection + residual + fused bn2 (per-batch) ----------------
__global__ void __launch_bounds__(256,2) k_outproj(
        const float* __restrict__ ow, const float* __restrict__ ob,
        const float* __restrict__ x, const float* __restrict__ g2,
        const float* __restrict__ bb2, int b){
    extern __shared__ float smp[];
    float* As = smp;
    float* Bs = smp + 2*64*36;
    int m0 = blockIdx.y*64, p0 = blockIdx.x*128;
    float acc[2][4][4];
    #pragma unroll
    for(int a=0;a<2;a++){ 
        #pragma unroll
        for(int nn=0;nn<4;nn++){ 
            #pragma unroll
            for(int cc=0;cc<4;cc++) acc[a][nn][cc]=0.f; } }
    gemm_core<2,512>(ow, g_attn + b*NC*HW, m0, p0, As, Bs, acc);
    int tid=threadIdx.x, lane=tid&31, wid=tid>>5;
    int g=lane>>2, t=lane&3;
    int mbase=(wid&1)*32, nbase=(wid>>1)*32;
    #pragma unroll
    for(int mt=0;mt<2;mt++){
        int mr = m0 + mbase + mt*16 + g;
        float bi0=ob[mr], bi1=ob[mr+8];
        float s0=g2[mr]*rsqrtf(1.0f+EPSBN), s1=g2[mr+8]*rsqrtf(1.0f+EPSBN);
        float c0=bb2[mr], c1=bb2[mr+8];
        #pragma unroll
        for(int nt=0;nt<4;nt++){
            int n = p0 + nbase + nt*8 + 2*t;
            int off0 = (b*NC + mr)*HW + n;
            int off1 = (b*NC + mr+8)*HW + n;
            float2 xv0 = *(const float2*)&x[off0];
            float2 xv1 = *(const float2*)&x[off1];
            float2 v0 = { xv0.x + acc[mt][nt][0] + bi0, xv0.y + acc[mt][nt][1] + bi0 };
            float2 v1 = { xv1.x + acc[mt][nt][2] + bi1, xv1.y + acc[mt][nt][3] + bi1 };
            *(float2*)&g_x2[off0] = v0;
            *(float2*)&g_x2[off1] = v1;
            float2 n0v = { v0.x*s0+c0, v0.y*s0+c0 };
            float2 n1v = { v1.x*s1+c1, v1.y*s1+c1 };
            *(float2*)&g_xn2[off0] = n0v;
            *(float2*)&g_xn2[off1] = n1v;
        }
    }
}

// ---------------- 8) MLP conv1 (per-batch) ----------------
__global__ void __launch_bounds__(256,2) k_mlp1(
        const float* __restrict__ w, const float* __restrict__ bias, int b){
    extern __shared__ float smp[];
    float* As = smp;
    float* Bs = smp + 2*128*36;
    int m0 = blockIdx.y*128, p0 = blockIdx.x*128;
    float acc[4][4][4];
    #pragma unroll
    for(int a=0;a<4;a++){ 
        #pragma unroll
        for(int nn=0;nn<4;nn++){ 
            #pragma unroll
            for(int cc=0;cc<4;cc++) acc[a][nn][cc]=0.f; } }
    gemm_core<4,512>(w, g_xn2 + b*NC*HW, m0, p0, As, Bs, acc);
    int tid=threadIdx.x, lane=tid&31, wid=tid>>5;
    int g=lane>>2, t=lane&3;
    int mbase=(wid&1)*64, nbase=(wid>>1)*32;
    #pragma unroll
    for(int mt=0;mt<4;mt++){
        int mr = m0 + mbase + mt*16 + g;
        float bi0=bias[mr], bi1=bias[mr+8];
        #pragma unroll
        for(int nt=0;nt<4;nt++){
            int n = p0 + nbase + nt*8 + 2*t;
            float2 v0 = { gelu_exact(acc[mt][nt][0]+bi0), gelu_exact(acc[mt][nt][1]+bi0) };
            float2 v1 = { gelu_exact(acc[mt][nt][2]+bi1), gelu_exact(acc[mt][nt][3]+bi1) };
            *(float2*)&g_h1[(b*2048 + mr)*HW + n]   = v0;
            *(float2*)&g_h1[(b*2048 + mr+8)*HW + n] = v1;
        }
    }
}

// ---------------- 9) MLP conv2 + residual (per-batch) ----------------
__global__ void __launch_bounds__(256,2) k_mlp2(
        const float* __restrict__ w, const float* __restrict__ bias,
        float* __restrict__ out, int b){
    extern __shared__ float smp[];
    float* As = smp;
    float* Bs = smp + 2*64*36;
    int m0 = blockIdx.y*64, p0 = blockIdx.x*128;
    float acc[2][4][4];
    #pragma unroll
    for(int a=0;a<2;a++){ 
        #pragma unroll
        for(int nn=0;nn<4;nn++){ 
            #pragma unroll
            for(int cc=0;cc<4;cc++) acc[a][nn][cc]=0.f; } }
    gemm_core<2,2048>(w, g_h1 + b*2048*HW, m0, p0, As, Bs, acc);
    int tid=threadIdx.x, lane=tid&31, wid=tid>>5;
    int g=lane>>2, t=lane&3;
    int mbase=(wid&1)*32, nbase=(wid>>1)*32;
    #pragma unroll
    for(int mt=0;mt<2;mt++){
        int mr = m0 + mbase + mt*16 + g;
        float bi0=bias[mr], bi1=bias[mr+8];
        #pragma unroll
        for(int nt=0;nt<4;nt++){
            int n = p0 + nbase + nt*8 + 2*t;
            int off0 = (b*NC + mr)*HW + n;
            int off1 = (b*NC + mr+8)*HW + n;
            float2 r0 = *(const float2*)&g_x2[off0];
            float2 r1 = *(const float2*)&g_x2[off1];
            float2 v0 = { r0.x + acc[mt][nt][0] + bi0, r0.y + acc[mt][nt][1] + bi0 };
            float2 v1 = { r1.x + acc[mt][nt][2] + bi1, r1.y + acc[mt][nt][3] + bi1 };
            *(float2*)&out[off0] = v0;
            *(float2*)&out[off1] = v1;
        }
    }
}

// ---------------- launch ----------------
extern "C" void kernel_launch(void* const* d_in, const int* in_sizes, int n_in,
                              void* d_out, int out_size){
    const float* x    = (const float*)d_in[0];
    const float* bn1g = (const float*)d_in[1];
    const float* bn1b = (const float*)d_in[2];
    const float* bn2g = (const float*)d_in[3];
    const float* bn2b = (const float*)d_in[4];
    const float* qw   = (const float*)d_in[5];
    const float* kw   = (const float*)d_in[6];
    const float* vw   = (const float*)d_in[7];
    const float* ow   = (const float*)d_in[8];
    const float* obv  = (const float*)d_in[9];
    const float* dw   = (const float*)d_in[10];
    const float* dwb  = (const float*)d_in[11];
    const float* pw   = (const float*)d_in[12];
    const float* cw1  = (const float*)d_in[13];
    const float* cb1  = (const float*)d_in[14];
    const float* cw2  = (const float*)d_in[15];
    const float* cb2  = (const float*)d_in[16];
    const float* cw3  = (const float*)d_in[17];
    const float* cb3  = (const float*)d_in[18];
    const float* mw1  = (const float*)d_in[19];
    const float* mb1  = (const float*)d_in[20];
    const float* mw2  = (const float*)d_in[21];
    const float* mb2  = (const float*)d_in[22];
    float* out = (float*)d_out;

    const int tab_smem  = (256*132 + 128*132 + 1024 + 512 + 256 + 256 + 128) * 4;
    const int gem2_smem = (2*64*36 + 2*32*132) * 4;
    const int gem4_smem = (2*128*36 + 2*32*132) * 4;

    static bool init = false;
    static cudaStream_t s1;
    static cudaEvent_t evF, evOff, evSamp, evInt, evEnd;
    if(!init){
        cudaStreamCreateWithFlags(&s1, cudaStreamNonBlocking);
        cudaEventCreateWithFlags(&evF,    cudaEventDisableTiming);
        cudaEventCreateWithFlags(&evOff,  cudaEventDisableTiming);
        cudaEventCreateWithFlags(&evSamp, cudaEventDisableTiming);
        cudaEventCreateWithFlags(&evInt,  cudaEventDisableTiming);
        cudaEventCreateWithFlags(&evEnd,  cudaEventDisableTiming);
        cudaFuncSetAttribute(k_tab,     cudaFuncAttributeMaxDynamicSharedMemorySize, tab_smem);
        cudaFuncSetAttribute(k_outproj, cudaFuncAttributeMaxDynamicSharedMemorySize, gem2_smem);
        cudaFuncSetAttribute(k_mlp1,    cudaFuncAttributeMaxDynamicSharedMemorySize, gem4_smem);
        cudaFuncSetAttribute(k_mlp2,    cudaFuncAttributeMaxDynamicSharedMemorySize, gem2_smem);
        init = true;
    }

    // ---- front path ----
    cudaEventRecord(evF, 0);
    cudaStreamWaitEvent(s1, evF, 0);
    k_tab<<<66,512,tab_smem,s1>>>(cw1,cb1,cw2,cb2,cw3,cb3);

    k_qproj  <<<dim3(8,16),128>>>(x,qw,bn1g,bn1b);
    k_offsets<<<256,256>>>(dw,dwb,pw);
    cudaEventRecord(evOff, 0);

    k_sample <<<dim3(16,8,2),256>>>(x,kw,vw,bn1g,bn1b);
    cudaEventRecord(evSamp, 0);

    cudaStreamWaitEvent(s1, evOff, 0);
    k_interp <<<4096,256,0,s1>>>();
    cudaEventRecord(evInt, s1);

    // ---- batch-pipelined tail ----
    // stream 0: batch 0 (needs interp from s1)
    cudaStreamWaitEvent(0, evInt, 0);
    k_attn   <<<dim3(8,8),128>>>(0);
    k_outproj<<<dim3(8,8),256,gem2_smem>>>(ow,obv,x,bn2g,bn2b,0);
    k_mlp1   <<<dim3(8,16),256,gem4_smem>>>(mw1,mb1,0);
    k_mlp2   <<<dim3(8,8),256,gem2_smem>>>(mw2,mb2,out,0);

    // stream 1: batch 1 (needs sample from stream 0; interp already in-stream)
    cudaStreamWaitEvent(s1, evSamp, 0);
    k_attn   <<<dim3(8,8),128,0,s1>>>(1);
    k_outproj<<<dim3(8,8),256,gem2_smem,s1>>>(ow,obv,x,bn2g,bn2b,1);
    k_mlp1   <<<dim3(8,16),256,gem4_smem,s1>>>(mw1,mb1,1);
    k_mlp2   <<<dim3(8,8),256,gem2_smem,s1>>>(mw2,mb2,out,1);
    cudaEventRecord(evEnd, s1);
    cudaStreamWaitEvent(0, evEnd, 0);
}

// round 15
// speedup vs baseline: 1.0124x; 1.0115x over previous
#include <cuda_runtime.h>
#include <cstdint>

#define NB 2
#define NC 512
#define NH 32
#define NW 32
#define HW 1024
#define NG 8
#define DH 64
#define BG 16
#define JD 64
#define EPSBN 1e-5f

#define TABN 129
#define FMAXF 1.43f
#define TSTEP (2.0f*FMAXF/128.0f)
#define TINV  (128.0f/(2.0f*FMAXF))

// ---------------- scratch ----------------
__device__ float g_q[NB*NC*HW];
__device__ float g_qt[BG*HW*DH];
__device__ float g_grid[BG*JD*2];
__device__ float g_k[BG*DH*JD];
__device__ float g_v[BG*DH*JD];
__device__ float g_bias[BG*HW*JD];   // [bg][j][i]
__device__ float g_attn[NB*NC*HW];
__device__ float g_x2[NB*NC*HW];
__device__ float g_xn2[NB*NC*HW];
__device__ float g_h1[NB*2048*HW];
__device__ float g_part[2*NB*NC*HW]; // split-K partials for mlp2
__device__ float g_tab[TABN*TABN];

__device__ __forceinline__ float gelu_exact(float x){
    return 0.5f*x*(1.0f+erff(x*0.7071067811865476f));
}
__device__ __forceinline__ uint32_t f2tf(float v){
    uint32_t r; asm("cvt.rna.tf32.f32 %0, %1;" : "=r"(r) : "f"(v)); return r;
}
__device__ __forceinline__ float tfr(float v){ return __uint_as_float(f2tf(v)); }
__device__ __forceinline__ void mma_tf32(float c[4], const uint32_t a[4], const uint32_t b[2]){
    asm volatile("mma.sync.aligned.m16n8k8.row.col.f32.tf32.tf32.f32 "
        "{%0,%1,%2,%3}, {%4,%5,%6,%7}, {%8,%9}, {%0,%1,%2,%3};"
        : "+f"(c[0]),"+f"(c[1]),"+f"(c[2]),"+f"(c[3])
        : "r"(a[0]),"r"(a[1]),"r"(a[2]),"r"(a[3]),"r"(b[0]),"r"(b[1]));
}
__device__ __forceinline__ void cpa16(float* smem, const float* gmem){
    uint32_t s = (uint32_t)__cvta_generic_to_shared(smem);
    asm volatile("cp.async.ca.shared.global [%0], [%1], 16;" :: "r"(s), "l"(gmem));
}

// ---------------- 1) q grouped 1x1 conv, bn1 fused into load ----------------
__global__ void k_qproj(const float* __restrict__ x, const float* __restrict__ qw,
                        const float* __restrict__ g1, const float* __restrict__ b1){
    __shared__ float ws[DH*DH];
    __shared__ float xs[DH*128];
    int bg = blockIdx.y; int b = bg>>3, g = bg&7;
    int p0 = blockIdx.x*128;
    int tid = threadIdx.x;
    const float* wsrc = qw + g*DH*DH;
    for(int i=tid;i<DH*DH;i+=128) ws[i]=wsrc[i];
    const float* xsrc = x + (b*NC + g*DH)*HW + p0;
    for(int k=0;k<DH;k++){
        int c = g*DH + k;
        float s = g1[c]*rsqrtf(1.0f+EPSBN);
        float bb = b1[c];
        xs[k*128+tid] = xsrc[k*HW+tid]*s + bb;
    }
    __syncthreads();
    float acc[DH];
    #pragma unroll
    for(int o=0;o<DH;o++) acc[o]=0.f;
    for(int c=0;c<DH;c++){
        float xv = xs[c*128+tid];
        #pragma unroll
        for(int o=0;o<DH;o++) acc[o] += ws[o*DH+c]*xv;
    }
    float* qdst = g_q + (b*NC + g*DH)*HW + p0 + tid;
    #pragma unroll
    for(int o=0;o<DH;o++) qdst[o*HW]=acc[o];
    float* qt = g_qt + (bg*HW + p0 + tid)*DH;
    #pragma unroll
    for(int o=0;o<DH;o+=4)
        *(float4*)&qt[o] = make_float4(acc[o],acc[o+1],acc[o+2],acc[o+3]);
}

// ---------------- 2) offsets: TWO warps per (bg,pos), taps split by ky ----------------
__global__ void __launch_bounds__(256) k_offsets(
        const float* __restrict__ dw, const float* __restrict__ dwb,
        const float* __restrict__ pw){
    __shared__ float dwt[36*DH];
    __shared__ float pws[2*DH];
    __shared__ float dbs[DH];
    __shared__ float h0[8][32], h1[8][32];
    int tid = threadIdx.x;
    for(int i=tid;i<DH*36;i+=256){ int ch=i/36, tap=i%36; dwt[tap*DH+ch]=dw[i]; }
    for(int i=tid;i<2*DH;i+=256) pws[i]=pw[i];
    for(int i=tid;i<DH;i+=256) dbs[i]=dwb[i];
    __syncthreads();
    int wid = tid>>5, lane = tid&31;
    int pl = wid>>1;
    int par = wid&1;
    int gidx = blockIdx.x*4 + pl;
    int bg = gidx>>6, pos = gidx&63;
    int oy=pos>>3, ox=pos&7;
    int c0 = lane*2;
    const float* qt = g_qt + bg*HW*DH;
    float s0=0.f, s1=0.f;
    int ky0 = par*3;
    #pragma unroll
    for(int kk=0;kk<3;kk++){
        int ky = ky0+kk;
        int iy = oy*4-1+ky;
        if(iy<0||iy>=NH) continue;
        #pragma unroll
        for(int kx=0;kx<6;kx++){
            int ix = ox*4-1+kx;
            if(ix<0||ix>=NW) continue;
            float2 v = *(const float2*)&qt[(iy*NW+ix)*DH + c0];
            float2 w = *(const float2*)&dwt[(ky*6+kx)*DH + c0];
            s0 += v.x*w.x;
            s1 += v.y*w.y;
        }
    }
    h0[wid][lane]=s0; h1[wid][lane]=s1;
    __syncthreads();
    if(par==0){
        float t0 = s0 + h0[wid+1][lane];
        float t1 = s1 + h1[wid+1][lane];
        t0 = gelu_exact(t0 + dbs[c0]);
        t1 = gelu_exact(t1 + dbs[c0+1]);
        float a0 = t0*pws[c0]    + t1*pws[c0+1];
        float a1 = t0*pws[DH+c0] + t1*pws[DH+c0+1];
        #pragma unroll
        for(int o=16;o>0;o>>=1){
            a0 += __shfl_xor_sync(0xffffffffu, a0, o);
            a1 += __shfl_xor_sync(0xffffffffu, a1, o);
        }
        if(lane==0){
            float vx = (float)ox + tanhf(a0)*4.0f;
            float vy = (float)oy + tanhf(a1)*4.0f;
            g_grid[(bg*JD+pos)*2+0] = 2.0f*vx/7.0f - 1.0f;
            g_grid[(bg*JD+pos)*2+1] = 2.0f*vy/7.0f - 1.0f;
        }
    }
}

// ---------------- 3) grid_sample (bn fused) + k/v conv; o-dim split in 2 ----------------
__global__ void k_sample(const float* __restrict__ x,
                         const float* __restrict__ kw, const float* __restrict__ vw,
                         const float* __restrict__ g1, const float* __restrict__ b1){
    __shared__ float kvs[DH*8];
    __shared__ float kws[32*DH];
    __shared__ float vws[32*DH];
    __shared__ float scs[DH], bcs[DH];
    int bg=blockIdx.x, jq=blockIdx.y, oh=blockIdx.z*32, tid=threadIdx.x;
    int b=bg>>3, g=bg&7;
    for(int i=tid;i<32*DH;i+=256){ kws[i]=kw[g*DH*DH+oh*DH+i]; vws[i]=vw[g*DH*DH+oh*DH+i]; }
    if(tid<DH){
        int c = g*DH + tid;
        scs[tid] = g1[c]*rsqrtf(1.0f+EPSBN);
        bcs[tid] = b1[c];
    }
    __syncthreads();
    const float* img = x + (b*NC+g*DH)*HW;
    for(int i=tid;i<DH*8;i+=256){
        int c=i>>3, jl=i&7, j=jq*8+jl;
        float s=scs[c], bb=bcs[c];
        float nx=g_grid[(bg*JD+j)*2], ny=g_grid[(bg*JD+j)*2+1];
        float gx=(nx+1.0f)*16.0f-0.5f;
        float gy2=(ny+1.0f)*16.0f-0.5f;
        float x0f=floorf(gx), y0f=floorf(gy2);
        float wx=gx-x0f, wy=gy2-y0f;
        int x0=(int)x0f, y0=(int)y0f;
        const float* im=img+c*HW;
        float v00=0.f,v01=0.f,v10=0.f,v11=0.f;
        bool xi0 = (x0>=0)&&(x0<NW), xi1 = (x0+1>=0)&&(x0+1<NW);
        bool yi0 = (y0>=0)&&(y0<NH), yi1 = (y0+1>=0)&&(y0+1<NH);
        if(yi0){ if(xi0) v00=im[y0*NW+x0]*s+bb; if(xi1) v01=im[y0*NW+x0+1]*s+bb; }
        if(yi1){ if(xi0) v10=im[(y0+1)*NW+x0]*s+bb; if(xi1) v11=im[(y0+1)*NW+x0+1]*s+bb; }
        kvs[c*8+jl] = v00*(1.f-wx)*(1.f-wy)+v01*wx*(1.f-wy)+v10*(1.f-wx)*wy+v11*wx*wy;
    }
    __syncthreads();
    {
        int ol=tid>>3, jl=tid&7, o=oh+ol, j=jq*8+jl;
        float ka=0.f,va=0.f;
        for(int c=0;c<DH;c++){
            float kvv=kvs[c*8+jl];
            ka += kws[ol*DH+c]*kvv;
            va += vws[ol*DH+c]*kvv;
        }
        g_k[bg*DH*JD + o*JD + j] = ka;
        g_v[bg*DH*JD + o*JD + j] = va;
    }
}

// ---------------- 4) CPB table on 129x129 feature grid (mma) ----------------
__global__ void __launch_bounds__(512,1) k_tab(
        const float* __restrict__ w1, const float* __restrict__ b1,
        const float* __restrict__ w2, const float* __restrict__ b2,
        const float* __restrict__ w3, const float* __restrict__ b3){
    extern __shared__ float sm[];
    float* Hs  = sm;
    float* Ws  = Hs + 256*132;
    float* red = Ws + 128*132;
    float* f0s = red + 1024;
    float* f1s = f0s + 256;
    float* b2s = f1s + 256;
    float* w3s = b2s + 128;
    float* w1s = w3s + 128;
    float* b1s = w1s + 256;
    int tid = threadIdx.x;
    int pt0 = blockIdx.x*256;
    if(tid<256){
        int pt = pt0 + tid;
        int v = pt/TABN;
        int u = pt - v*TABN;
        f0s[tid] = -FMAXF + (float)u*TSTEP;
        f1s[tid] = -FMAXF + (float)v*TSTEP;
        w1s[tid] = w1[tid];
    }
    if(tid<128){ b1s[tid]=b1[tid]; b2s[tid]=b2[tid]; w3s[tid]=w3[tid]; }
    #pragma unroll
    for(int it=0; it<8; it++){
        int idx = tid + it*512;
        int k = idx>>5, n4 = (idx&31)*4;
        float4 v = *(const float4*)&w2[k*128 + n4];
        *(float4*)&Ws[k*132 + n4] = make_float4(tfr(v.x),tfr(v.y),tfr(v.z),tfr(v.w));
    }
    __syncthreads();
    #pragma unroll
    for(int it=0; it<16; it++){
        int idx = tid + it*512;
        int m = idx>>5, k4 = (idx&31)*4;
        float f0 = f0s[m], f1 = f1s[m];
        float4 wv0 = *(const float4*)&w1s[k4];
        float4 wv1 = *(const float4*)&w1s[128+k4];
        float4 bv  = *(const float4*)&b1s[k4];
        float4 h;
        h.x = tfr(fmaxf(f0*wv0.x + f1*wv1.x + bv.x, 0.f));
        h.y = tfr(fmaxf(f0*wv0.y + f1*wv1.y + bv.y, 0.f));
        h.z = tfr(fmaxf(f0*wv0.z + f1*wv1.z + bv.z, 0.f));
        h.w = tfr(fmaxf(f0*wv0.w + f1*wv1.w + bv.w, 0.f));
        *(float4*)&Hs[m*132 + k4] = h;
    }
    __syncthreads();

    int lane = tid&31, wid = tid>>5;
    int g = lane>>2, t = lane&3;
    int mbase = (wid&3)*64, nbase = (wid>>2)*32;
    float acc[4][4][4];
    #pragma unroll
    for(int a=0;a<4;a++){
        #pragma unroll
        for(int nn=0;nn<4;nn++){
            #pragma unroll
            for(int cc=0;cc<4;cc++) acc[a][nn][cc]=0.f; } }

    #pragma unroll 4
    for(int kc=0;kc<16;kc++){
        int K = kc*8;
        uint32_t af[4][4];
        #pragma unroll
        for(int mt=0;mt<4;mt++){
            const float* ap = Hs + (mbase+mt*16+g)*132 + K + t;
            af[mt][0] = __float_as_uint(ap[0]);
            af[mt][1] = __float_as_uint(ap[8*132]);
            af[mt][2] = __float_as_uint(ap[4]);
            af[mt][3] = __float_as_uint(ap[8*132+4]);
        }
        uint32_t bf[4][2];
        #pragma unroll
        for(int nt=0;nt<4;nt++){
            const float* bp = Ws + (K+t)*132 + nbase + nt*8 + g;
            bf[nt][0] = __float_as_uint(bp[0]);
            bf[nt][1] = __float_as_uint(bp[4*132]);
        }
        #pragma unroll
        for(int mt=0;mt<4;mt++){
            #pragma unroll
            for(int nt=0;nt<4;nt++) mma_tf32(acc[mt][nt], af[mt], bf[nt]);
        }
    }
    #pragma unroll
    for(int mt=0;mt<4;mt++){
        float pA=0.f, pB=0.f;
        #pragma unroll
        for(int nt=0;nt<4;nt++){
            int n = nbase + nt*8 + 2*t;
            float ba=b2s[n], bb=b2s[n+1], wa=w3s[n], wb=w3s[n+1];
            pA += fmaxf(acc[mt][nt][0]+ba,0.f)*wa + fmaxf(acc[mt][nt][1]+bb,0.f)*wb;
            pB += fmaxf(acc[mt][nt][2]+ba,0.f)*wa + fmaxf(acc[mt][nt][3]+bb,0.f)*wb;
        }
        pA += __shfl_xor_sync(0xffffffffu, pA, 1);
        pA += __shfl_xor_sync(0xffffffffu, pA, 2);
        pB += __shfl_xor_sync(0xffffffffu, pB, 1);
        pB += __shfl_xor_sync(0xffffffffu, pB, 2);
        if(t==0){
            int rA = mbase+mt*16+g;
            red[rA*4 + (wid>>2)]     = pA;
            red[(rA+8)*4 + (wid>>2)] = pB;
        }
    }
    __syncthreads();
    if(tid<256 && pt0+tid<TABN*TABN)
        g_tab[pt0+tid] = b3[0] + red[tid*4] + red[tid*4+1] + red[tid*4+2] + red[tid*4+3];
}

// ---------------- 5) bias interpolation -> g_bias [bg][j][i] ----------------
__global__ void k_interp(){
    int idx = blockIdx.x*256 + threadIdx.x;
    int bg = idx>>16;
    int j  = (idx>>10)&63;
    int i  = idx&1023;
    float qx = 2.0f*(float)(i&31)*(1.0f/31.0f) - 1.0f;
    float qy = 2.0f*(float)(i>>5)*(1.0f/31.0f) - 1.0f;
    float2 kv = *(const float2*)&g_grid[(bg*JD+j)*2];
    float p0 = qx - kv.x, p1 = qy - kv.y;
    float f0 = copysignf(log1pf(fabsf(p0)), p0);
    float f1 = copysignf(log1pf(fabsf(p1)), p1);
    float u = fminf(fmaxf((f0+FMAXF)*TINV, 0.0f), 127.999f);
    float v = fminf(fmaxf((f1+FMAXF)*TINV, 0.0f), 127.999f);
    int iu=(int)u, iv=(int)v;
    float fu=u-(float)iu, fv=v-(float)iv;
    const float* t0 = g_tab + iv*TABN + iu;
    float a = t0[0]    + fu*(t0[1]-t0[0]);
    float b = t0[TABN] + fu*(t0[TABN+1]-t0[TABN]);
    g_bias[idx] = a + fv*(b-a);
}

// ---------------- 6) attention ----------------
__global__ void k_attn(){
    __shared__ float ks[DH*JD];
    __shared__ float vs[DH*JD];
    int bg=blockIdx.y, it=blockIdx.x, tid=threadIdx.x;
    int b=bg>>3, g=bg&7;
    for(int i=tid;i<DH*JD;i+=128){ ks[i]=g_k[bg*DH*JD+i]; vs[i]=g_v[bg*DH*JD+i]; }
    __syncthreads();
    int i = it*128 + tid;
    const float* qp = g_q + (b*NC+g*DH)*HW + i;
    float sim[JD];
    #pragma unroll
    for(int j=0;j<JD;j++) sim[j]=0.f;
    for(int d=0;d<DH;d++){
        float qv = qp[d*HW];
        #pragma unroll
        for(int j=0;j<JD;j++) sim[j] += qv*ks[d*JD+j];
    }
    const float scale = 0.125f;
    const float* bp = g_bias + bg*JD*HW + i;
    float m=-1e30f;
    #pragma unroll
    for(int j=0;j<JD;j++){ sim[j] = sim[j]*scale + bp[j*HW]; m=fmaxf(m,sim[j]); }
    float ssum=0.f;
    #pragma unroll
    for(int j=0;j<JD;j++){ sim[j]=expf(sim[j]-m); ssum+=sim[j]; }
    float inv = 1.0f/ssum;
    float* op = g_attn + (b*NC+g*DH)*HW + i;
    for(int d=0;d<DH;d++){
        float a=0.f;
        #pragma unroll
        for(int j=0;j<JD;j++) a += sim[j]*vs[d*JD+j];
        op[d*HW] = a*inv;
    }
}

// ---------------- 2-buffer cp.async tf32 GEMM core (KSTRIDE = A row stride) ----------------
template<int MT, int KTOT, int KSTRIDE>
__device__ __forceinline__ void gemm_core(const float* __restrict__ A,
                                          const float* __restrict__ Bb,
                                          int m0, int p0,
                                          float* As, float* Bs,
                                          float (*acc)[4][4]){
    constexpr int BM = MT*32;
    constexpr int NA = BM/32;
    constexpr int NS = KTOT/32;
    int tid=threadIdx.x, lane=tid&31, wid=tid>>5;
    int g=lane>>2, t=lane&3;
    int mbase=(wid&1)*MT*16, nbase=(wid>>1)*32;

    auto prefetch = [&](int s, int buf){
        int k0 = s*32;
        float* Ad = As + buf*BM*36;
        float* Bd = Bs + buf*32*132;
        #pragma unroll
        for(int ia=0; ia<NA; ia++){
            int idx = tid + ia*256;
            cpa16(Ad + (idx>>3)*36 + (idx&7)*4, A + (m0+(idx>>3))*KSTRIDE + k0 + (idx&7)*4);
        }
        #pragma unroll
        for(int ib=0; ib<4; ib++){
            int idx = tid + ib*256;
            cpa16(Bd + (idx>>5)*132 + (idx&31)*4, Bb + (k0+(idx>>5))*HW + p0 + (idx&31)*4);
        }
        asm volatile("cp.async.commit_group;");
    };

    prefetch(0,0);
    for(int s=0; s<NS; s++){
        if(s+1<NS){
            prefetch(s+1,(s+1)&1);
            asm volatile("cp.async.wait_group 1;");
        } else {
            asm volatile("cp.async.wait_group 0;");
        }
        __syncthreads();
        const float* Ac = As + (s&1)*BM*36;
        const float* Bc = Bs + (s&1)*32*132;
        #pragma unroll
        for(int kc=0;kc<4;kc++){
            int K = kc*8;
            uint32_t af[MT][4];
            #pragma unroll
            for(int mt=0;mt<MT;mt++){
                const float* ap = Ac + (mbase+mt*16+g)*36 + K + t;
                af[mt][0] = __float_as_uint(ap[0]);
                af[mt][1] = __float_as_uint(ap[8*36]);
                af[mt][2] = __float_as_uint(ap[4]);
                af[mt][3] = __float_as_uint(ap[8*36+4]);
            }
            uint32_t bf[4][2];
            #pragma unroll
            for(int nt=0;nt<4;nt++){
                const float* bp = Bc + (K+t)*132 + nbase + nt*8 + g;
                bf[nt][0] = __float_as_uint(bp[0]);
                bf[nt][1] = __float_as_uint(bp[4*132]);
            }
            #pragma unroll
            for(int mt=0;mt<MT;mt++){
                #pragma unroll
                for(int nt=0;nt<4;nt++) mma_tf32(acc[mt][nt], af[mt], bf[nt]);
            }
        }
        __syncthreads();
    }
}

// ---------------- 7) out projection + residual + fused bn2 ----------------
__global__ void __launch_bounds__(256,2) k_outproj(
        const float* __restrict__ ow, const float* __restrict__ ob,
        const float* __restrict__ x, const float* __restrict__ g2,
        const float* __restrict__ bb2){
    extern __shared__ float smp[];
    float* As = smp;
    float* Bs = smp + 2*64*36;
    int m0 = blockIdx.y*64, n0 = blockIdx.x*128;
    int b = n0>>10, p0 = n0&1023;
    float acc[2][4][4];
    #pragma unroll
    for(int a=0;a<2;a++){ 
        #pragma unroll
        for(int nn=0;nn<4;nn++){ 
            #pragma unroll
            for(int cc=0;cc<4;cc++) acc[a][nn][cc]=0.f; } }
    gemm_core<2,512,512>(ow, g_attn + b*NC*HW, m0, p0, As, Bs, acc);
    int tid=threadIdx.x, lane=tid&31, wid=tid>>5;
    int g=lane>>2, t=lane&3;
    int mbase=(wid&1)*32, nbase=(wid>>1)*32;
    #pragma unroll
    for(int mt=0;mt<2;mt++){
        int mr = m0 + mbase + mt*16 + g;
        float bi0=ob[mr], bi1=ob[mr+8];
        float s0=g2[mr]*rsqrtf(1.0f+EPSBN), s1=g2[mr+8]*rsqrtf(1.0f+EPSBN);
        float c0=bb2[mr], c1=bb2[mr+8];
        #pragma unroll
        for(int nt=0;nt<4;nt++){
            int n = p0 + nbase + nt*8 + 2*t;
            int off0 = (b*NC + mr)*HW + n;
            int off1 = (b*NC + mr+8)*HW + n;
            float2 xv0 = *(const float2*)&x[off0];
            float2 xv1 = *(const float2*)&x[off1];
            float2 v0 = { xv0.x + acc[mt][nt][0] + bi0, xv0.y + acc[mt][nt][1] + bi0 };
            float2 v1 = { xv1.x + acc[mt][nt][2] + bi1, xv1.y + acc[mt][nt][3] + bi1 };
            *(float2*)&g_x2[off0] = v0;
            *(float2*)&g_x2[off1] = v1;
            float2 n0v = { v0.x*s0+c0, v0.y*s0+c0 };
            float2 n1v = { v1.x*s1+c1, v1.y*s1+c1 };
            *(float2*)&g_xn2[off0] = n0v;
            *(float2*)&g_xn2[off1] = n1v;
        }
    }
}

// ---------------- 8) MLP conv1 ----------------
__global__ void __launch_bounds__(256,2) k_mlp1(
        const float* __restrict__ w, const float* __restrict__ bias){
    extern __shared__ float smp[];
    float* As = smp;
    float* Bs = smp + 2*128*36;
    int m0 = blockIdx.y*128, n0 = blockIdx.x*128;
    int b = n0>>10, p0 = n0&1023;
    float acc[4][4][4];
    #pragma unroll
    for(int a=0;a<4;a++){ 
        #pragma unroll
        for(int nn=0;nn<4;nn++){ 
            #pragma unroll
            for(int cc=0;cc<4;cc++) acc[a][nn][cc]=0.f; } }
    gemm_core<4,512,512>(w, g_xn2 + b*NC*HW, m0, p0, As, Bs, acc);
    int tid=threadIdx.x, lane=tid&31, wid=tid>>5;
    int g=lane>>2, t=lane&3;
    int mbase=(wid&1)*64, nbase=(wid>>1)*32;
    #pragma unroll
    for(int mt=0;mt<4;mt++){
        int mr = m0 + mbase + mt*16 + g;
        float bi0=bias[mr], bi1=bias[mr+8];
        #pragma unroll
        for(int nt=0;nt<4;nt++){
            int n = p0 + nbase + nt*8 + 2*t;
            float2 v0 = { gelu_exact(acc[mt][nt][0]+bi0), gelu_exact(acc[mt][nt][1]+bi0) };
            float2 v1 = { gelu_exact(acc[mt][nt][2]+bi1), gelu_exact(acc[mt][nt][3]+bi1) };
            *(float2*)&g_h1[(b*2048 + mr)*HW + n]   = v0;
            *(float2*)&g_h1[(b*2048 + mr+8)*HW + n] = v1;
        }
    }
}

// ---------------- 9) MLP conv2 split-K: partials only ----------------
__global__ void __launch_bounds__(256,2) k_mlp2(
        const float* __restrict__ w){
    extern __shared__ float smp[];
    float* As = smp;
    float* Bs = smp + 2*64*36;
    int m0 = blockIdx.y*64, n0 = blockIdx.x*128;
    int kh = blockIdx.z;
    int b = n0>>10, p0 = n0&1023;
    float acc[2][4][4];
    #pragma unroll
    for(int a=0;a<2;a++){ 
        #pragma unroll
        for(int nn=0;nn<4;nn++){ 
            #pragma unroll
            for(int cc=0;cc<4;cc++) acc[a][nn][cc]=0.f; } }
    gemm_core<2,1024,2048>(w + kh*1024,
                           g_h1 + b*2048*HW + kh*1024*HW,
                           m0, p0, As, Bs, acc);
    int tid=threadIdx.x, lane=tid&31, wid=tid>>5;
    int g=lane>>2, t=lane&3;
    int mbase=(wid&1)*32, nbase=(wid>>1)*32;
    float* dst = g_part + kh*(NB*NC*HW);
    #pragma unroll
    for(int mt=0;mt<2;mt++){
        int mr = m0 + mbase + mt*16 + g;
        #pragma unroll
        for(int nt=0;nt<4;nt++){
            int n = p0 + nbase + nt*8 + 2*t;
            int off0 = (b*NC + mr)*HW + n;
            int off1 = (b*NC + mr+8)*HW + n;
            *(float2*)&dst[off0] = make_float2(acc[mt][nt][0], acc[mt][nt][1]);
            *(float2*)&dst[off1] = make_float2(acc[mt][nt][2], acc[mt][nt][3]);
        }
    }
}

// ---------------- 10) combine: out = x2 + p0 + p1 + bias ----------------
__global__ void k_comb(const float* __restrict__ bias, float* __restrict__ out){
    int idx4 = blockIdx.x*256 + threadIdx.x;       // 262144
    int c = (idx4>>8)&(NC-1);
    float bi = bias[c];
    int base = idx4*4;
    float4 r  = *(const float4*)&g_x2[base];
    float4 a0 = *(const float4*)&g_part[base];
    float4 a1 = *(const float4*)&g_part[NB*NC*HW + base];
    float4 o = { r.x + a0.x + a1.x + bi,
                 r.y + a0.y + a1.y + bi,
                 r.z + a0.z + a1.z + bi,
                 r.w + a0.w + a1.w + bi };
    *(float4*)&out[base] = o;
}

// ---------------- launch ----------------
extern "C" void kernel_launch(void* const* d_in, const int* in_sizes, int n_in,
                              void* d_out, int out_size){
    const float* x    = (const float*)d_in[0];
    const float* bn1g = (const float*)d_in[1];
    const float* bn1b = (const float*)d_in[2];
    const float* bn2g = (const float*)d_in[3];
    const float* bn2b = (const float*)d_in[4];
    const float* qw   = (const float*)d_in[5];
    const float* kw   = (const float*)d_in[6];
    const float* vw   = (const float*)d_in[7];
    const float* ow   = (const float*)d_in[8];
    const float* obv  = (const float*)d_in[9];
    const float* dw   = (const float*)d_in[10];
    const float* dwb  = (const float*)d_in[11];
    const float* pw   = (const float*)d_in[12];
    const float* cw1  = (const float*)d_in[13];
    const float* cb1  = (const float*)d_in[14];
    const float* cw2  = (const float*)d_in[15];
    const float* cb2  = (const float*)d_in[16];
    const float* cw3  = (const float*)d_in[17];
    const float* cb3  = (const float*)d_in[18];
    const float* mw1  = (const float*)d_in[19];
    const float* mb1  = (const float*)d_in[20];
    const float* mw2  = (const float*)d_in[21];
    const float* mb2  = (const float*)d_in[22];
    float* out = (float*)d_out;

    const int tab_smem  = (256*132 + 128*132 + 1024 + 512 + 256 + 256 + 128) * 4;
    const int gem2_smem = (2*64*36 + 2*32*132) * 4;
    const int gem4_smem = (2*128*36 + 2*32*132) * 4;

    static bool init = false;
    static cudaStream_t s1;
    static cudaEvent_t evF, evOff, evInt;
    if(!init){
        cudaStreamCreateWithFlags(&s1, cudaStreamNonBlocking);
        cudaEventCreateWithFlags(&evF,   cudaEventDisableTiming);
        cudaEventCreateWithFlags(&evOff, cudaEventDisableTiming);
        cudaEventCreateWithFlags(&evInt, cudaEventDisableTiming);
        cudaFuncSetAttribute(k_tab,     cudaFuncAttributeMaxDynamicSharedMemorySize, tab_smem);
        cudaFuncSetAttribute(k_outproj, cudaFuncAttributeMaxDynamicSharedMemorySize, gem2_smem);
        cudaFuncSetAttribute(k_mlp1,    cudaFuncAttributeMaxDynamicSharedMemorySize, gem4_smem);
        cudaFuncSetAttribute(k_mlp2,    cudaFuncAttributeMaxDynamicSharedMemorySize, gem2_smem);
        init = true;
    }

    cudaEventRecord(evF, 0);
    cudaStreamWaitEvent(s1, evF, 0);
    k_tab<<<66,512,tab_smem,s1>>>(cw1,cb1,cw2,cb2,cw3,cb3);

    k_qproj  <<<dim3(8,16),128>>>(x,qw,bn1g,bn1b);
    k_offsets<<<256,256>>>(dw,dwb,pw);
    cudaEventRecord(evOff, 0);

    k_sample <<<dim3(16,8,2),256>>>(x,kw,vw,bn1g,bn1b);

    cudaStreamWaitEvent(s1, evOff, 0);
    k_interp <<<4096,256,0,s1>>>();
    cudaEventRecord(evInt, s1);

    cudaStreamWaitEvent(0, evInt, 0);
    k_attn   <<<dim3(8,16),128>>>();
    k_outproj<<<dim3(16,8),256,gem2_smem>>>(ow,obv,x,bn2g,bn2b);
    k_mlp1   <<<dim3(16,16),256,gem4_smem>>>(mw1,mb1);
    k_mlp2   <<<dim3(16,8,2),256,gem2_smem>>>(mw2);
    k_comb   <<<1024,256>>>(mb2,out);
}

// round 16
// speedup vs baseline: 1.0610x; 1.0480x over previous
#include <cuda_runtime.h>
#include <cstdint>

#define NB 2
#define NC 512
#define NH 32
#define NW 32
#define HW 1024
#define NG 8
#define DH 64
#define BG 16
#define JD 64
#define EPSBN 1e-5f

#define TABN 129
#define FMAXF 1.43f
#define TSTEP (2.0f*FMAXF/128.0f)
#define TINV  (128.0f/(2.0f*FMAXF))

// ---------------- scratch ----------------
__device__ float g_q[NB*NC*HW];
__device__ float g_qt[BG*HW*DH];
__device__ float g_grid[BG*JD*2];
__device__ float g_k[BG*DH*JD];
__device__ float g_v[BG*DH*JD];
__device__ float g_bias[BG*HW*JD];   // [bg][j][i]
__device__ float g_attn[NB*NC*HW];
__device__ float g_x2[NB*NC*HW];
__device__ float g_xn2[NB*NC*HW];
__device__ float g_h1[NB*2048*HW];
__device__ float g_tab[TABN*TABN];

__device__ __forceinline__ float gelu_exact(float x){
    return 0.5f*x*(1.0f+erff(x*0.7071067811865476f));
}
__device__ __forceinline__ uint32_t f2tf(float v){
    uint32_t r; asm("cvt.rna.tf32.f32 %0, %1;" : "=r"(r) : "f"(v)); return r;
}
__device__ __forceinline__ float tfr(float v){ return __uint_as_float(f2tf(v)); }
__device__ __forceinline__ void mma_tf32(float c[4], const uint32_t a[4], const uint32_t b[2]){
    asm volatile("mma.sync.aligned.m16n8k8.row.col.f32.tf32.tf32.f32 "
        "{%0,%1,%2,%3}, {%4,%5,%6,%7}, {%8,%9}, {%0,%1,%2,%3};"
        : "+f"(c[0]),"+f"(c[1]),"+f"(c[2]),"+f"(c[3])
        : "r"(a[0]),"r"(a[1]),"r"(a[2]),"r"(a[3]),"r"(b[0]),"r"(b[1]));
}
__device__ __forceinline__ void cpa16(float* smem, const float* gmem){
    uint32_t s = (uint32_t)__cvta_generic_to_shared(smem);
    asm volatile("cp.async.ca.shared.global [%0], [%1], 16;" :: "r"(s), "l"(gmem));
}

// ---------------- 1) q grouped 1x1 conv, bn1 fused, TRANSPOSED weights ----------------
__global__ void k_qproj(const float* __restrict__ x, const float* __restrict__ qw,
                        const float* __restrict__ g1, const float* __restrict__ b1){
    __shared__ float wst[DH*DH];     // [c][o]  (transposed)
    __shared__ float xs[DH*128];
    int bg = blockIdx.y; int b = bg>>3, g = bg&7;
    int p0 = blockIdx.x*128;
    int tid = threadIdx.x;
    const float* wsrc = qw + g*DH*DH;
    // smem-contiguous writes; strided gmem reads (tiny, L2-resident)
    for(int i=tid;i<DH*DH;i+=128){ int c=i>>6, o=i&63; wst[c*DH+o]=wsrc[o*DH+c]; }
    const float* xsrc = x + (b*NC + g*DH)*HW + p0;
    for(int k=0;k<DH;k++){
        int c = g*DH + k;
        float s = g1[c]*rsqrtf(1.0f+EPSBN);
        float bb = b1[c];
        xs[k*128+tid] = xsrc[k*HW+tid]*s + bb;
    }
    __syncthreads();
    float4 acc[16];
    #pragma unroll
    for(int o=0;o<16;o++) acc[o]=make_float4(0.f,0.f,0.f,0.f);
    for(int c=0;c<DH;c++){
        float xv = xs[c*128+tid];
        const float4* wp = (const float4*)&wst[c*DH];
        #pragma unroll
        for(int o4=0;o4<16;o4++){
            float4 w = wp[o4];
            acc[o4].x += w.x*xv;
            acc[o4].y += w.y*xv;
            acc[o4].z += w.z*xv;
            acc[o4].w += w.w*xv;
        }
    }
    float* qdst = g_q + (b*NC + g*DH)*HW + p0 + tid;
    #pragma unroll
    for(int o4=0;o4<16;o4++){
        qdst[(o4*4+0)*HW]=acc[o4].x;
        qdst[(o4*4+1)*HW]=acc[o4].y;
        qdst[(o4*4+2)*HW]=acc[o4].z;
        qdst[(o4*4+3)*HW]=acc[o4].w;
    }
    float* qt = g_qt + (bg*HW + p0 + tid)*DH;
    #pragma unroll
    for(int o4=0;o4<16;o4++)
        *(float4*)&qt[o4*4] = acc[o4];
}

// ---------------- 2) offsets: TWO warps per (bg,pos), taps split by ky ----------------
__global__ void __launch_bounds__(256) k_offsets(
        const float* __restrict__ dw, const float* __restrict__ dwb,
        const float* __restrict__ pw){
    __shared__ float dwt[36*DH];
    __shared__ float pws[2*DH];
    __shared__ float dbs[DH];
    __shared__ float h0[8][32], h1[8][32];
    int tid = threadIdx.x;
    for(int i=tid;i<DH*36;i+=256){ int ch=i/36, tap=i%36; dwt[tap*DH+ch]=dw[i]; }
    for(int i=tid;i<2*DH;i+=256) pws[i]=pw[i];
    for(int i=tid;i<DH;i+=256) dbs[i]=dwb[i];
    __syncthreads();
    int wid = tid>>5, lane = tid&31;
    int pl = wid>>1;
    int par = wid&1;
    int gidx = blockIdx.x*4 + pl;
    int bg = gidx>>6, pos = gidx&63;
    int oy=pos>>3, ox=pos&7;
    int c0 = lane*2;
    const float* qt = g_qt + bg*HW*DH;
    float s0=0.f, s1=0.f;
    int ky0 = par*3;
    #pragma unroll
    for(int kk=0;kk<3;kk++){
        int ky = ky0+kk;
        int iy = oy*4-1+ky;
        if(iy<0||iy>=NH) continue;
        #pragma unroll
        for(int kx=0;kx<6;kx++){
            int ix = ox*4-1+kx;
            if(ix<0||ix>=NW) continue;
            float2 v = *(const float2*)&qt[(iy*NW+ix)*DH + c0];
            float2 w = *(const float2*)&dwt[(ky*6+kx)*DH + c0];
            s0 += v.x*w.x;
            s1 += v.y*w.y;
        }
    }
    h0[wid][lane]=s0; h1[wid][lane]=s1;
    __syncthreads();
    if(par==0){
        float t0 = s0 + h0[wid+1][lane];
        float t1 = s1 + h1[wid+1][lane];
        t0 = gelu_exact(t0 + dbs[c0]);
        t1 = gelu_exact(t1 + dbs[c0+1]);
        float a0 = t0*pws[c0]    + t1*pws[c0+1];
        float a1 = t0*pws[DH+c0] + t1*pws[DH+c0+1];
        #pragma unroll
        for(int o=16;o>0;o>>=1){
            a0 += __shfl_xor_sync(0xffffffffu, a0, o);
            a1 += __shfl_xor_sync(0xffffffffu, a1, o);
        }
        if(lane==0){
            float vx = (float)ox + tanhf(a0)*4.0f;
            float vy = (float)oy + tanhf(a1)*4.0f;
            g_grid[(bg*JD+pos)*2+0] = 2.0f*vx/7.0f - 1.0f;
            g_grid[(bg*JD+pos)*2+1] = 2.0f*vy/7.0f - 1.0f;
        }
    }
}

// ---------------- 3) grid_sample (bn fused) + k/v conv; o-dim split in 2 ----------------
__global__ void k_sample(const float* __restrict__ x,
                         const float* __restrict__ kw, const float* __restrict__ vw,
                         const float* __restrict__ g1, const float* __restrict__ b1){
    __shared__ float kvs[DH*8];
    __shared__ float kws[32*DH];
    __shared__ float vws[32*DH];
    __shared__ float scs[DH], bcs[DH];
    int bg=blockIdx.x, jq=blockIdx.y, oh=blockIdx.z*32, tid=threadIdx.x;
    int b=bg>>3, g=bg&7;
    for(int i=tid;i<32*DH;i+=256){ kws[i]=kw[g*DH*DH+oh*DH+i]; vws[i]=vw[g*DH*DH+oh*DH+i]; }
    if(tid<DH){
        int c = g*DH + tid;
        scs[tid] = g1[c]*rsqrtf(1.0f+EPSBN);
        bcs[tid] = b1[c];
    }
    __syncthreads();
    const float* img = x + (b*NC+g*DH)*HW;
    for(int i=tid;i<DH*8;i+=256){
        int c=i>>3, jl=i&7, j=jq*8+jl;
        float s=scs[c], bb=bcs[c];
        float nx=g_grid[(bg*JD+j)*2], ny=g_grid[(bg*JD+j)*2+1];
        float gx=(nx+1.0f)*16.0f-0.5f;
        float gy2=(ny+1.0f)*16.0f-0.5f;
        float x0f=floorf(gx), y0f=floorf(gy2);
        float wx=gx-x0f, wy=gy2-y0f;
        int x0=(int)x0f, y0=(int)y0f;
        const float* im=img+c*HW;
        float v00=0.f,v01=0.f,v10=0.f,v11=0.f;
        bool xi0 = (x0>=0)&&(x0<NW), xi1 = (x0+1>=0)&&(x0+1<NW);
        bool yi0 = (y0>=0)&&(y0<NH), yi1 = (y0+1>=0)&&(y0+1<NH);
        if(yi0){ if(xi0) v00=im[y0*NW+x0]*s+bb; if(xi1) v01=im[y0*NW+x0+1]*s+bb; }
        if(yi1){ if(xi0) v10=im[(y0+1)*NW+x0]*s+bb; if(xi1) v11=im[(y0+1)*NW+x0+1]*s+bb; }
        kvs[c*8+jl] = v00*(1.f-wx)*(1.f-wy)+v01*wx*(1.f-wy)+v10*(1.f-wx)*wy+v11*wx*wy;
    }
    __syncthreads();
    {
        int ol=tid>>3, jl=tid&7, o=oh+ol, j=jq*8+jl;
        float ka=0.f,va=0.f;
        for(int c=0;c<DH;c++){
            float kvv=kvs[c*8+jl];
            ka += kws[ol*DH+c]*kvv;
            va += vws[ol*DH+c]*kvv;
        }
        g_k[bg*DH*JD + o*JD + j] = ka;
        g_v[bg*DH*JD + o*JD + j] = va;
    }
}

// ---------------- 4) CPB table on 129x129 feature grid (mma) ----------------
__global__ void __launch_bounds__(512,1) k_tab(
        const float* __restrict__ w1, const float* __restrict__ b1,
        const float* __restrict__ w2, const float* __restrict__ b2,
        const float* __restrict__ w3, const float* __restrict__ b3){
    extern __shared__ float sm[];
    float* Hs  = sm;
    float* Ws  = Hs + 256*132;
    float* red = Ws + 128*132;
    float* f0s = red + 1024;
    float* f1s = f0s + 256;
    float* b2s = f1s + 256;
    float* w3s = b2s + 128;
    float* w1s = w3s + 128;
    float* b1s = w1s + 256;
    int tid = threadIdx.x;
    int pt0 = blockIdx.x*256;
    if(tid<256){
        int pt = pt0 + tid;
        int v = pt/TABN;
        int u = pt - v*TABN;
        f0s[tid] = -FMAXF + (float)u*TSTEP;
        f1s[tid] = -FMAXF + (float)v*TSTEP;
        w1s[tid] = w1[tid];
    }
    if(tid<128){ b1s[tid]=b1[tid]; b2s[tid]=b2[tid]; w3s[tid]=w3[tid]; }
    #pragma unroll
    for(int it=0; it<8; it++){
        int idx = tid + it*512;
        int k = idx>>5, n4 = (idx&31)*4;
        float4 v = *(const float4*)&w2[k*128 + n4];
        *(float4*)&Ws[k*132 + n4] = make_float4(tfr(v.x),tfr(v.y),tfr(v.z),tfr(v.w));
    }
    __syncthreads();
    #pragma unroll
    for(int it=0; it<16; it++){
        int idx = tid + it*512;
        int m = idx>>5, k4 = (idx&31)*4;
        float f0 = f0s[m], f1 = f1s[m];
        float4 wv0 = *(const float4*)&w1s[k4];
        float4 wv1 = *(const float4*)&w1s[128+k4];
        float4 bv  = *(const float4*)&b1s[k4];
        float4 h;
        h.x = tfr(fmaxf(f0*wv0.x + f1*wv1.x + bv.x, 0.f));
        h.y = tfr(fmaxf(f0*wv0.y + f1*wv1.y + bv.y, 0.f));
        h.z = tfr(fmaxf(f0*wv0.z + f1*wv1.z + bv.z, 0.f));
        h.w = tfr(fmaxf(f0*wv0.w + f1*wv1.w + bv.w, 0.f));
        *(float4*)&Hs[m*132 + k4] = h;
    }
    __syncthreads();

    int lane = tid&31, wid = tid>>5;
    int g = lane>>2, t = lane&3;
    int mbase = (wid&3)*64, nbase = (wid>>2)*32;
    float acc[4][4][4];
    #pragma unroll
    for(int a=0;a<4;a++){
        #pragma unroll
        for(int nn=0;nn<4;nn++){
            #pragma unroll
            for(int cc=0;cc<4;cc++) acc[a][nn][cc]=0.f; } }

    #pragma unroll 4
    for(int kc=0;kc<16;kc++){
        int K = kc*8;
        uint32_t af[4][4];
        #pragma unroll
        for(int mt=0;mt<4;mt++){
            const float* ap = Hs + (mbase+mt*16+g)*132 + K + t;
            af[mt][0] = __float_as_uint(ap[0]);
            af[mt][1] = __float_as_uint(ap[8*132]);
            af[mt][2] = __float_as_uint(ap[4]);
            af[mt][3] = __float_as_uint(ap[8*132+4]);
        }
        uint32_t bf[4][2];
        #pragma unroll
        for(int nt=0;nt<4;nt++){
            const float* bp = Ws + (K+t)*132 + nbase + nt*8 + g;
            bf[nt][0] = __float_as_uint(bp[0]);
            bf[nt][1] = __float_as_uint(bp[4*132]);
        }
        #pragma unroll
        for(int mt=0;mt<4;mt++){
            #pragma unroll
            for(int nt=0;nt<4;nt++) mma_tf32(acc[mt][nt], af[mt], bf[nt]);
        }
    }
    #pragma unroll
    for(int mt=0;mt<4;mt++){
        float pA=0.f, pB=0.f;
        #pragma unroll
        for(int nt=0;nt<4;nt++){
            int n = nbase + nt*8 + 2*t;
            float ba=b2s[n], bb=b2s[n+1], wa=w3s[n], wb=w3s[n+1];
            pA += fmaxf(acc[mt][nt][0]+ba,0.f)*wa + fmaxf(acc[mt][nt][1]+bb,0.f)*wb;
            pB += fmaxf(acc[mt][nt][2]+ba,0.f)*wa + fmaxf(acc[mt][nt][3]+bb,0.f)*wb;
        }
        pA += __shfl_xor_sync(0xffffffffu, pA, 1);
        pA += __shfl_xor_sync(0xffffffffu, pA, 2);
        pB += __shfl_xor_sync(0xffffffffu, pB, 1);
        pB += __shfl_xor_sync(0xffffffffu, pB, 2);
        if(t==0){
            int rA = mbase+mt*16+g;
            red[rA*4 + (wid>>2)]     = pA;
            red[(rA+8)*4 + (wid>>2)] = pB;
        }
    }
    __syncthreads();
    if(tid<256 && pt0+tid<TABN*TABN)
        g_tab[pt0+tid] = b3[0] + red[tid*4] + red[tid*4+1] + red[tid*4+2] + red[tid*4+3];
}

// ---------------- 5) bias interpolation -> g_bias [bg][j][i] ----------------
__global__ void k_interp(){
    int idx = blockIdx.x*256 + threadIdx.x;
    int bg = idx>>16;
    int j  = (idx>>10)&63;
    int i  = idx&1023;
    float qx = 2.0f*(float)(i&31)*(1.0f/31.0f) - 1.0f;
    float qy = 2.0f*(float)(i>>5)*(1.0f/31.0f) - 1.0f;
    float2 kv = *(const float2*)&g_grid[(bg*JD+j)*2];
    float p0 = qx - kv.x, p1 = qy - kv.y;
    float f0 = copysignf(log1pf(fabsf(p0)), p0);
    float f1 = copysignf(log1pf(fabsf(p1)), p1);
    float u = fminf(fmaxf((f0+FMAXF)*TINV, 0.0f), 127.999f);
    float v = fminf(fmaxf((f1+FMAXF)*TINV, 0.0f), 127.999f);
    int iu=(int)u, iv=(int)v;
    float fu=u-(float)iu, fv=v-(float)iv;
    const float* t0 = g_tab + iv*TABN + iu;
    float a = t0[0]    + fu*(t0[1]-t0[0]);
    float b = t0[TABN] + fu*(t0[TABN+1]-t0[TABN]);
    g_bias[idx] = a + fv*(b-a);
}

// ---------------- 6) attention (float4 smem reads) ----------------
__global__ void k_attn(){
    __shared__ float ks[DH*JD];
    __shared__ float vs[DH*JD];
    int bg=blockIdx.y, it=blockIdx.x, tid=threadIdx.x;
    int b=bg>>3, g=bg&7;
    for(int i=tid;i<DH*JD;i+=128){ ks[i]=g_k[bg*DH*JD+i]; vs[i]=g_v[bg*DH*JD+i]; }
    __syncthreads();
    int i = it*128 + tid;
    const float* qp = g_q + (b*NC+g*DH)*HW + i;
    float sim[JD];
    #pragma unroll
    for(int j=0;j<JD;j++) sim[j]=0.f;
    for(int d=0;d<DH;d++){
        float qv = qp[d*HW];
        const float4* k4 = (const float4*)&ks[d*JD];
        #pragma unroll
        for(int j4=0;j4<16;j4++){
            float4 kv = k4[j4];
            sim[j4*4+0] += qv*kv.x;
            sim[j4*4+1] += qv*kv.y;
            sim[j4*4+2] += qv*kv.z;
            sim[j4*4+3] += qv*kv.w;
        }
    }
    const float scale = 0.125f;
    const float* bp = g_bias + bg*JD*HW + i;
    float m=-1e30f;
    #pragma unroll
    for(int j=0;j<JD;j++){ sim[j] = sim[j]*scale + bp[j*HW]; m=fmaxf(m,sim[j]); }
    float ssum=0.f;
    #pragma unroll
    for(int j=0;j<JD;j++){ sim[j]=expf(sim[j]-m); ssum+=sim[j]; }
    float inv = 1.0f/ssum;
    float* op = g_attn + (b*NC+g*DH)*HW + i;
    for(int d=0;d<DH;d++){
        const float4* v4 = (const float4*)&vs[d*JD];
        float a=0.f;
        #pragma unroll
        for(int j4=0;j4<16;j4++){
            float4 vv = v4[j4];
            a += sim[j4*4+0]*vv.x + sim[j4*4+1]*vv.y
               + sim[j4*4+2]*vv.z + sim[j4*4+3]*vv.w;
        }
        op[d*HW] = a*inv;
    }
}

// ---------------- 2-buffer cp.async tf32 GEMM core (r12, proven) ----------------
template<int MT, int KTOT>
__device__ __forceinline__ void gemm_core(const float* __restrict__ A,
                                          const float* __restrict__ Bb,
                                          int m0, int p0,
                                          float* As, float* Bs,
                                          float (*acc)[4][4]){
    constexpr int BM = MT*32;
    constexpr int NA = BM/32;
    constexpr int NS = KTOT/32;
    int tid=threadIdx.x, lane=tid&31, wid=tid>>5;
    int g=lane>>2, t=lane&3;
    int mbase=(wid&1)*MT*16, nbase=(wid>>1)*32;

    auto prefetch = [&](int s, int buf){
        int k0 = s*32;
        float* Ad = As + buf*BM*36;
        float* Bd = Bs + buf*32*132;
        #pragma unroll
        for(int ia=0; ia<NA; ia++){
            int idx = tid + ia*256;
            cpa16(Ad + (idx>>3)*36 + (idx&7)*4, A + (m0+(idx>>3))*KTOT + k0 + (idx&7)*4);
        }
        #pragma unroll
        for(int ib=0; ib<4; ib++){
            int idx = tid + ib*256;
            cpa16(Bd + (idx>>5)*132 + (idx&31)*4, Bb + (k0+(idx>>5))*HW + p0 + (idx&31)*4);
        }
        asm volatile("cp.async.commit_group;");
    };

    prefetch(0,0);
    for(int s=0; s<NS; s++){
        if(s+1<NS){
            prefetch(s+1,(s+1)&1);
            asm volatile("cp.async.wait_group 1;");
        } else {
            asm volatile("cp.async.wait_group 0;");
        }
        __syncthreads();
        const float* Ac = As + (s&1)*BM*36;
        const float* Bc = Bs + (s&1)*32*132;
        #pragma unroll
        for(int kc=0;kc<4;kc++){
            int K = kc*8;
            uint32_t af[MT][4];
            #pragma unroll
            for(int mt=0;mt<MT;mt++){
                const float* ap = Ac + (mbase+mt*16+g)*36 + K + t;
                af[mt][0] = __float_as_uint(ap[0]);
                af[mt][1] = __float_as_uint(ap[8*36]);
                af[mt][2] = __float_as_uint(ap[4]);
                af[mt][3] = __float_as_uint(ap[8*36+4]);
            }
            uint32_t bf[4][2];
            #pragma unroll
            for(int nt=0;nt<4;nt++){
                const float* bp = Bc + (K+t)*132 + nbase + nt*8 + g;
                bf[nt][0] = __float_as_uint(bp[0]);
                bf[nt][1] = __float_as_uint(bp[4*132]);
            }
            #pragma unroll
            for(int mt=0;mt<MT;mt++){
                #pragma unroll
                for(int nt=0;nt<4;nt++) mma_tf32(acc[mt][nt], af[mt], bf[nt]);
            }
        }
        __syncthreads();
    }
}

// ---------------- 7) out projection + residual + fused bn2 ----------------
__global__ void __launch_bounds__(256,2) k_outproj(
        const float* __restrict__ ow, const float* __restrict__ ob,
        const float* __restrict__ x, const float* __restrict__ g2,
        const float* __restrict__ bb2){
    extern __shared__ float smp[];
    float* As = smp;
    float* Bs = smp + 2*64*36;
    int m0 = blockIdx.y*64, n0 = blockIdx.x*128;
    int b = n0>>10, p0 = n0&1023;
    float acc[2][4][4];
    #pragma unroll
    for(int a=0;a<2;a++){ 
        #pragma unroll
        for(int nn=0;nn<4;nn++){ 
            #pragma unroll
            for(int cc=0;cc<4;cc++) acc[a][nn][cc]=0.f; } }
    gemm_core<2,512>(ow, g_attn + b*NC*HW, m0, p0, As, Bs, acc);
    int tid=threadIdx.x, lane=tid&31, wid=tid>>5;
    int g=lane>>2, t=lane&3;
    int mbase=(wid&1)*32, nbase=(wid>>1)*32;
    #pragma unroll
    for(int mt=0;mt<2;mt++){
        int mr = m0 + mbase + mt*16 + g;
        float bi0=ob[mr], bi1=ob[mr+8];
        float s0=g2[mr]*rsqrtf(1.0f+EPSBN), s1=g2[mr+8]*rsqrtf(1.0f+EPSBN);
        float c0=bb2[mr], c1=bb2[mr+8];
        #pragma unroll
        for(int nt=0;nt<4;nt++){
            int n = p0 + nbase + nt*8 + 2*t;
            int off0 = (b*NC + mr)*HW + n;
            int off1 = (b*NC + mr+8)*HW + n;
            float2 xv0 = *(const float2*)&x[off0];
            float2 xv1 = *(const float2*)&x[off1];
            float2 v0 = { xv0.x + acc[mt][nt][0] + bi0, xv0.y + acc[mt][nt][1] + bi0 };
            float2 v1 = { xv1.x + acc[mt][nt][2] + bi1, xv1.y + acc[mt][nt][3] + bi1 };
            *(float2*)&g_x2[off0] = v0;
            *(float2*)&g_x2[off1] = v1;
            float2 n0v = { v0.x*s0+c0, v0.y*s0+c0 };
            float2 n1v = { v1.x*s1+c1, v1.y*s1+c1 };
            *(float2*)&g_xn2[off0] = n0v;
            *(float2*)&g_xn2[off1] = n1v;
        }
    }
}

// ---------------- 8) MLP conv1 ----------------
__global__ void __launch_bounds__(256,2) k_mlp1(
        const float* __restrict__ w, const float* __restrict__ bias){
    extern __shared__ float smp[];
    float* As = smp;
    float* Bs = smp + 2*128*36;
    int m0 = blockIdx.y*128, n0 = blockIdx.x*128;
    int b = n0>>10, p0 = n0&1023;
    float acc[4][4][4];
    #pragma unroll
    for(int a=0;a<4;a++){ 
        #pragma unroll
        for(int nn=0;nn<4;nn++){ 
            #pragma unroll
            for(int cc=0;cc<4;cc++) acc[a][nn][cc]=0.f; } }
    gemm_core<4,512>(w, g_xn2 + b*NC*HW, m0, p0, As, Bs, acc);
    int tid=threadIdx.x, lane=tid&31, wid=tid>>5;
    int g=lane>>2, t=lane&3;
    int mbase=(wid&1)*64, nbase=(wid>>1)*32;
    #pragma unroll
    for(int mt=0;mt<4;mt++){
        int mr = m0 + mbase + mt*16 + g;
        float bi0=bias[mr], bi1=bias[mr+8];
        #pragma unroll
        for(int nt=0;nt<4;nt++){
            int n = p0 + nbase + nt*8 + 2*t;
            float2 v0 = { gelu_exact(acc[mt][nt][0]+bi0), gelu_exact(acc[mt][nt][1]+bi0) };
            float2 v1 = { gelu_exact(acc[mt][nt][2]+bi1), gelu_exact(acc[mt][nt][3]+bi1) };
            *(float2*)&g_h1[(b*2048 + mr)*HW + n]   = v0;
            *(float2*)&g_h1[(b*2048 + mr+8)*HW + n] = v1;
        }
    }
}

// ---------------- 9) MLP conv2 + residual ----------------
__global__ void __launch_bounds__(256,2) k_mlp2(
        const float* __restrict__ w, const float* __restrict__ bias,
        float* __restrict__ out){
    extern __shared__ float smp[];
    float* As = smp;
    float* Bs = smp + 2*64*36;
    int m0 = blockIdx.y*64, n0 = blockIdx.x*128;
    int b = n0>>10, p0 = n0&1023;
    float acc[2][4][4];
    #pragma unroll
    for(int a=0;a<2;a++){ 
        #pragma unroll
        for(int nn=0;nn<4;nn++){ 
            #pragma unroll
            for(int cc=0;cc<4;cc++) acc[a][nn][cc]=0.f; } }
    gemm_core<2,2048>(w, g_h1 + b*2048*HW, m0, p0, As, Bs, acc);
    int tid=threadIdx.x, lane=tid&31, wid=tid>>5;
    int g=lane>>2, t=lane&3;
    int mbase=(wid&1)*32, nbase=(wid>>1)*32;
    #pragma unroll
    for(int mt=0;mt<2;mt++){
        int mr = m0 + mbase + mt*16 + g;
        float bi0=bias[mr], bi1=bias[mr+8];
        #pragma unroll
        for(int nt=0;nt<4;nt++){
            int n = p0 + nbase + nt*8 + 2*t;
            int off0 = (b*NC + mr)*HW + n;
            int off1 = (b*NC + mr+8)*HW + n;
            float2 r0 = *(const float2*)&g_x2[off0];
            float2 r1 = *(const float2*)&g_x2[off1];
            float2 v0 = { r0.x + acc[mt][nt][0] + bi0, r0.y + acc[mt][nt][1] + bi0 };
            float2 v1 = { r1.x + acc[mt][nt][2] + bi1, r1.y + acc[mt][nt][3] + bi1 };
            *(float2*)&out[off0] = v0;
            *(float2*)&out[off1] = v1;
        }
    }
}

// ---------------- launch ----------------
extern "C" void kernel_launch(void* const* d_in, const int* in_sizes, int n_in,
                              void* d_out, int out_size){
    const float* x    = (const float*)d_in[0];
    const float* bn1g = (const float*)d_in[1];
    const float* bn1b = (const float*)d_in[2];
    const float* bn2g = (const float*)d_in[3];
    const float* bn2b = (const float*)d_in[4];
    const float* qw   = (const float*)d_in[5];
    const float* kw   = (const float*)d_in[6];
    const float* vw   = (const float*)d_in[7];
    const float* ow   = (const float*)d_in[8];
    const float* obv  = (const float*)d_in[9];
    const float* dw   = (const float*)d_in[10];
    const float* dwb  = (const float*)d_in[11];
    const float* pw   = (const float*)d_in[12];
    const float* cw1  = (const float*)d_in[13];
    const float* cb1  = (const float*)d_in[14];
    const float* cw2  = (const float*)d_in[15];
    const float* cb2  = (const float*)d_in[16];
    const float* cw3  = (const float*)d_in[17];
    const float* cb3  = (const float*)d_in[18];
    const float* mw1  = (const float*)d_in[19];
    const float* mb1  = (const float*)d_in[20];
    const float* mw2  = (const float*)d_in[21];
    const float* mb2  = (const float*)d_in[22];
    float* out = (float*)d_out;

    const int tab_smem  = (256*132 + 128*132 + 1024 + 512 + 256 + 256 + 128) * 4;
    const int gem2_smem = (2*64*36 + 2*32*132) * 4;
    const int gem4_smem = (2*128*36 + 2*32*132) * 4;

    static bool init = false;
    static cudaStream_t s1;
    static cudaEvent_t evF, evOff, evInt;
    if(!init){
        cudaStreamCreateWithFlags(&s1, cudaStreamNonBlocking);
        cudaEventCreateWithFlags(&evF,   cudaEventDisableTiming);
        cudaEventCreateWithFlags(&evOff, cudaEventDisableTiming);
        cudaEventCreateWithFlags(&evInt, cudaEventDisableTiming);
        cudaFuncSetAttribute(k_tab,     cudaFuncAttributeMaxDynamicSharedMemorySize, tab_smem);
        cudaFuncSetAttribute(k_outproj, cudaFuncAttributeMaxDynamicSharedMemorySize, gem2_smem);
        cudaFuncSetAttribute(k_mlp1,    cudaFuncAttributeMaxDynamicSharedMemorySize, gem4_smem);
        cudaFuncSetAttribute(k_mlp2,    cudaFuncAttributeMaxDynamicSharedMemorySize, gem2_smem);
        init = true;
    }

    cudaEventRecord(evF, 0);
    cudaStreamWaitEvent(s1, evF, 0);
    k_tab<<<66,512,tab_smem,s1>>>(cw1,cb1,cw2,cb2,cw3,cb3);

    k_qproj  <<<dim3(8,16),128>>>(x,qw,bn1g,bn1b);
    k_offsets<<<256,256>>>(dw,dwb,pw);
    cudaEventRecord(evOff, 0);

    k_sample <<<dim3(16,8,2),256>>>(x,kw,vw,bn1g,bn1b);

    cudaStreamWaitEvent(s1, evOff, 0);
    k_interp <<<4096,256,0,s1>>>();
    cudaEventRecord(evInt, s1);

    cudaStreamWaitEvent(0, evInt, 0);
    k_attn   <<<dim3(8,16),128>>>();
    k_outproj<<<dim3(16,8),256,gem2_smem>>>(ow,obv,x,bn2g,bn2b);
    k_mlp1   <<<dim3(16,16),256,gem4_smem>>>(mw1,mb1);
    k_mlp2   <<<dim3(16,8),256,gem2_smem>>>(mw2,mb2,out);
}